// round 1
// baseline (speedup 1.0000x reference)
#include <cuda_runtime.h>
#include <cstdint>

// ---------------------------------------------------------------------------
// GraphSAGE 3-layer forward on B200 (sm_100a). Round 1: correct fp32 baseline.
//   L1: mean-agg x (128-d) -> GEMM; L2/L3: GEMM -> mean-agg (post-GEMM rewrite)
//   out = L2-normalize(relu chain)
// Scratch lives in __device__ globals (no allocation allowed).
// ---------------------------------------------------------------------------

#define MAX_N   50000
#define MAX_D   2048
#define MAX_D3  1024

static __device__ float g_P  [(long long)MAX_N * MAX_D];   // h @ W_l products
static __device__ float g_AGG[(long long)MAX_N * MAX_D];   // scatter accumulator
static __device__ float g_H1 [(long long)MAX_N * MAX_D];
static __device__ float g_H2 [(long long)MAX_N * MAX_D];
static __device__ float g_H3 [(long long)MAX_N * MAX_D3];
static __device__ float g_cnt   [MAX_N];
static __device__ float g_invcnt[MAX_N];
static __device__ int   g_is64;

// ---------------------------------------------------------------------------
// edge_index dtype sniffer: reference says int64, but JAX with x64 disabled
// silently produces int32. For int64 values < 50000 every odd 32-bit word is 0;
// for int32 the odd-indexed words are real dst/src values (nonzero w.h.p.).
// ---------------------------------------------------------------------------
__global__ void detect_dtype_kernel(const int* __restrict__ words, int npairs) {
    __shared__ int found;
    if (threadIdx.x == 0) found = 0;
    __syncthreads();
    for (int i = threadIdx.x; i < npairs; i += blockDim.x)
        if (words[2 * i + 1] != 0) found = 1;
    __syncthreads();
    if (threadIdx.x == 0) g_is64 = found ? 0 : 1;
}

__device__ __forceinline__ int edge_at(const void* ei, long long idx, int is64) {
    return is64 ? (int)((const long long*)ei)[idx] : ((const int*)ei)[idx];
}

// ---------------------------------------------------------------------------
// degree count + reciprocal
// ---------------------------------------------------------------------------
__global__ void count_deg_kernel(const void* __restrict__ ei, int E) {
    int e = blockIdx.x * blockDim.x + threadIdx.x;
    if (e >= E) return;
    int d = edge_at(ei, (long long)E + e, g_is64);
    atomicAdd(&g_cnt[d], 1.0f);
}

__global__ void inv_cnt_kernel(int N) {
    int i = blockIdx.x * blockDim.x + threadIdx.x;
    if (i < N) g_invcnt[i] = 1.0f / fmaxf(g_cnt[i], 1.0f);
}

// ---------------------------------------------------------------------------
// warp-per-edge scatter add: AGG[dst] += S[src]   (D multiple of 128)
// ---------------------------------------------------------------------------
__global__ void scatter_add_kernel(const float* __restrict__ S,
                                   const void* __restrict__ ei,
                                   float* __restrict__ AGG, int E, int D) {
    const int gw   = (blockIdx.x * blockDim.x + threadIdx.x) >> 5;
    const int lane = threadIdx.x & 31;
    if (gw >= E) return;
    const int is64 = g_is64;
    const int s = edge_at(ei, gw, is64);
    const int d = edge_at(ei, (long long)E + gw, is64);
    const float4* srow = (const float4*)(S + (long long)s * D);
    float* drow = AGG + (long long)d * D;
    const int n4 = D >> 2;
    for (int c = lane; c < n4; c += 32) {
        float4 v = srow[c];
        atomicAdd(drow + 4 * c + 0, v.x);
        atomicAdd(drow + 4 * c + 1, v.y);
        atomicAdd(drow + 4 * c + 2, v.z);
        atomicAdd(drow + 4 * c + 3, v.w);
    }
}

// scale rows of M_ (N x D) by invcnt[row]  (used for layer-1 mean)
__global__ void scale_rows_kernel(float* __restrict__ Mat, int N, int D) {
    long long i = (long long)blockIdx.x * blockDim.x + threadIdx.x;
    if (i >= (long long)N * D) return;
    int r = (int)(i / D);
    Mat[i] *= g_invcnt[r];
}

// ---------------------------------------------------------------------------
// SGEMM: C[M,N] = act( A[M,K] @ B[K,N] + addmat*rowscale + bias )
// 128x128 block tile, BK=8, 8x8 per-thread, double-buffered smem. 256 thr.
// Requires K%8==0, N%128==0 (true here: K in {128,2048}, N in {1024,2048}).
// ---------------------------------------------------------------------------
__global__ __launch_bounds__(256, 2)
void sgemm_kernel(const float* __restrict__ A, const float* __restrict__ B,
                  float* __restrict__ C,
                  const float* __restrict__ addmat,
                  const float* __restrict__ rowscale,
                  const float* __restrict__ bias,
                  int M, int K, int N, int do_relu) {
    __shared__ float As[2][8][128];
    __shared__ float Bs[2][8][128];

    const int tid = threadIdx.x;
    const int bm = blockIdx.y, bn = blockIdx.x;

    // global-load mapping
    const int a_row = tid >> 1;          // 0..127
    const int a_col = (tid & 1) * 4;     // 0 or 4
    const int b_row = tid >> 5;          // 0..7
    const int b_col = (tid & 31) * 4;    // 0..124

    const int  grow    = bm * 128 + a_row;
    const bool a_valid = grow < M;
    const float* Aptr = A + (long long)grow * K + a_col;
    const float* Bptr = B + (long long)b_row * N + bn * 128 + b_col;

    const int ty = tid >> 4;   // 0..15 -> rows ty*8..
    const int tx = tid & 15;   // 0..15 -> cols tx*8..

    float acc[8][8];
#pragma unroll
    for (int i = 0; i < 8; i++)
#pragma unroll
        for (int j = 0; j < 8; j++) acc[i][j] = 0.f;

    const int nk = K >> 3;

    // prologue: tile 0
    {
        float4 av = a_valid ? *(const float4*)Aptr : make_float4(0, 0, 0, 0);
        float4 bv = *(const float4*)Bptr;
        As[0][a_col + 0][a_row] = av.x;
        As[0][a_col + 1][a_row] = av.y;
        As[0][a_col + 2][a_row] = av.z;
        As[0][a_col + 3][a_row] = av.w;
        *(float4*)&Bs[0][b_row][b_col] = bv;
    }
    __syncthreads();

    for (int kt = 0; kt < nk; kt++) {
        const int cur = kt & 1;
        const bool has_next = (kt + 1) < nk;
        float4 av2 = make_float4(0, 0, 0, 0), bv2 = make_float4(0, 0, 0, 0);
        if (has_next) {
            if (a_valid) av2 = *(const float4*)(Aptr + (kt + 1) * 8);
            bv2 = *(const float4*)(Bptr + (long long)(kt + 1) * 8 * N);
        }
#pragma unroll
        for (int k = 0; k < 8; k++) {
            float a_frag[8], b_frag[8];
            *(float4*)&a_frag[0] = *(const float4*)&As[cur][k][ty * 8];
            *(float4*)&a_frag[4] = *(const float4*)&As[cur][k][ty * 8 + 4];
            *(float4*)&b_frag[0] = *(const float4*)&Bs[cur][k][tx * 8];
            *(float4*)&b_frag[4] = *(const float4*)&Bs[cur][k][tx * 8 + 4];
#pragma unroll
            for (int i = 0; i < 8; i++)
#pragma unroll
                for (int j = 0; j < 8; j++)
                    acc[i][j] += a_frag[i] * b_frag[j];
        }
        if (has_next) {
            const int nxt = cur ^ 1;
            As[nxt][a_col + 0][a_row] = av2.x;
            As[nxt][a_col + 1][a_row] = av2.y;
            As[nxt][a_col + 2][a_row] = av2.z;
            As[nxt][a_col + 3][a_row] = av2.w;
            *(float4*)&Bs[nxt][b_row][b_col] = bv2;
            __syncthreads();
        }
    }

    // epilogue
#pragma unroll
    for (int i = 0; i < 8; i++) {
        const int row = bm * 128 + ty * 8 + i;
        if (row >= M) continue;
        const long long rbase = (long long)row * N;
        const float rs = rowscale ? rowscale[row] : 1.0f;
#pragma unroll
        for (int j = 0; j < 8; j++) {
            const int col = bn * 128 + tx * 8 + j;
            float v = acc[i][j];
            if (addmat) v += addmat[rbase + col] * rs;
            if (bias)   v += bias[col];
            if (do_relu) v = fmaxf(v, 0.f);
            C[rbase + col] = v;
        }
    }
}

// ---------------------------------------------------------------------------
// row-wise L2 normalize: out = h / max(||h||, 1e-12). D = 1024, 256 threads.
// ---------------------------------------------------------------------------
__global__ void l2norm_kernel(const float* __restrict__ H, float* __restrict__ out) {
    const int row = blockIdx.x;
    const float4* h = (const float4*)H + (long long)row * 256;
    float4 v = h[threadIdx.x];
    float s = v.x * v.x + v.y * v.y + v.z * v.z + v.w * v.w;
#pragma unroll
    for (int o = 16; o; o >>= 1) s += __shfl_xor_sync(0xFFFFFFFFu, s, o);
    __shared__ float ws[8];
    if ((threadIdx.x & 31) == 0) ws[threadIdx.x >> 5] = s;
    __syncthreads();
    if (threadIdx.x < 8) {
        float t = ws[threadIdx.x];
#pragma unroll
        for (int o = 4; o; o >>= 1) t += __shfl_xor_sync(0xFFu, t, o);
        if (threadIdx.x == 0) ws[0] = t;
    }
    __syncthreads();
    const float inv = 1.0f / fmaxf(sqrtf(ws[0]), 1e-12f);
    float4 o4 = make_float4(v.x * inv, v.y * inv, v.z * inv, v.w * inv);
    ((float4*)out)[(long long)row * 256 + threadIdx.x] = o4;
}

// ---------------------------------------------------------------------------
// host driver
// ---------------------------------------------------------------------------
static inline void run_sgemm(const float* A, const float* B, float* C,
                             const float* addmat, const float* rowscale,
                             const float* bias, int M, int K, int N, int relu) {
    dim3 grid(N / 128, (M + 127) / 128);
    sgemm_kernel<<<grid, 256>>>(A, B, C, addmat, rowscale, bias, M, K, N, relu);
}

extern "C" void kernel_launch(void* const* d_in, const int* in_sizes, int n_in,
                              void* d_out, int out_size) {
    // metadata order: x, unused, edge_index, W1_l, W1_r, b1, W2_l, W2_r, b2,
    //                 W3_l, W3_r, b3
    const float* x   = (const float*)d_in[0];
    const void*  ei  = d_in[2];
    const float* W1l = (const float*)d_in[3];
    const float* W1r = (const float*)d_in[4];
    const float* b1  = (const float*)d_in[5];
    const float* W2l = (const float*)d_in[6];
    const float* W2r = (const float*)d_in[7];
    const float* b2  = (const float*)d_in[8];
    const float* W3l = (const float*)d_in[9];
    const float* W3r = (const float*)d_in[10];
    const float* b3  = (const float*)d_in[11];

    const int D1 = in_sizes[5];               // 2048
    const int D2 = in_sizes[8];               // 2048
    const int D3 = in_sizes[11];              // 1024
    const int F  = in_sizes[3] / D1;          // 128
    const int N  = in_sizes[0] / F;           // 50000
    const int E  = in_sizes[2] / 2;           // 400000

    float *P, *AGG, *H1, *H2, *H3, *cnt;
    cudaGetSymbolAddress((void**)&P,   g_P);
    cudaGetSymbolAddress((void**)&AGG, g_AGG);
    cudaGetSymbolAddress((void**)&H1,  g_H1);
    cudaGetSymbolAddress((void**)&H2,  g_H2);
    cudaGetSymbolAddress((void**)&H3,  g_H3);
    cudaGetSymbolAddress((void**)&cnt, g_cnt);

    float* out = (float*)d_out;

    const int TPB = 256;
    const int edge_blocks  = (E + TPB - 1) / TPB;
    const int warp_blocks  = (E * 32 + TPB - 1) / TPB;   // warp per edge

    // 0) dtype sniff + degrees
    detect_dtype_kernel<<<1, 256>>>((const int*)ei, E < 1024 ? E : 1024);
    cudaMemsetAsync(cnt, 0, (size_t)N * sizeof(float));
    count_deg_kernel<<<edge_blocks, TPB>>>(ei, E);
    inv_cnt_kernel<<<(N + TPB - 1) / TPB, TPB>>>(N);

    // ---- Layer 1: aggregate x (128-d) first, then GEMMs ----
    cudaMemsetAsync(AGG, 0, (size_t)N * F * sizeof(float));
    scatter_add_kernel<<<warp_blocks, TPB>>>(x, ei, AGG, E, F);
    {
        long long tot = (long long)N * F;
        scale_rows_kernel<<<(int)((tot + TPB - 1) / TPB), TPB>>>(AGG, N, F);
    }
    run_sgemm(AGG, W1l, P, nullptr, nullptr, nullptr, N, F, D1, 0);   // P = mean_x @ W1_l
    run_sgemm(x, W1r, H1, P, nullptr, b1, N, F, D1, 1);               // H1 = relu(x@W1_r + P + b1)

    // ---- Layer 2: GEMM -> aggregate (post-GEMM mean rewrite) ----
    run_sgemm(H1, W2l, P, nullptr, nullptr, nullptr, N, D1, D2, 0);   // P = H1 @ W2_l
    cudaMemsetAsync(AGG, 0, (size_t)N * D2 * sizeof(float));
    scatter_add_kernel<<<warp_blocks, TPB>>>(P, ei, AGG, E, D2);
    {
        float* invc; cudaGetSymbolAddress((void**)&invc, g_invcnt);
        run_sgemm(H1, W2r, H2, AGG, invc, b2, N, D1, D2, 1);          // H2 = relu(H1@W2_r + AGG/cnt + b2)

        // ---- Layer 3 ----
        run_sgemm(H2, W3l, P, nullptr, nullptr, nullptr, N, D2, D3, 0);
        cudaMemsetAsync(AGG, 0, (size_t)N * D3 * sizeof(float));
        scatter_add_kernel<<<warp_blocks, TPB>>>(P, ei, AGG, E, D3);
        run_sgemm(H2, W3r, H3, AGG, invc, b3, N, D2, D3, 1);          // H3 = relu(H2@W3_r + AGG/cnt + b3)
    }

    // ---- normalize ----
    l2norm_kernel<<<N, 256>>>(H3, out);
    (void)n_in; (void)out_size;
}

// round 3
// speedup vs baseline: 1.9902x; 1.9902x over previous
#include <cuda_runtime.h>
#include <cuda_bf16.h>
#include <cstdint>

// ===========================================================================
// GraphSAGE 3-layer forward, plain sm_100 target (no 'a' features!).
// Tensor cores via mma.sync.m16n8k16 bf16 (hi/lo split, 3 products, fp32 acc).
// cp.async 3-stage pipeline, ldmatrix with XOR swizzle, fused epilogue.
// ===========================================================================

#define NMAX 50000
#define DMAX 2048

static __device__ float g_P  [(long long)NMAX * DMAX];
static __device__ float g_AGG[(long long)NMAX * DMAX];
static __device__ float g_H  [(long long)NMAX * DMAX];
static __device__ float g_cnt   [NMAX];
static __device__ float g_invcnt[NMAX];
static __device__ int   g_is64;

static __device__ __nv_bfloat16 g_X_hi[(long long)NMAX * 256];
static __device__ __nv_bfloat16 g_X_lo[(long long)NMAX * 256];
static __device__ __nv_bfloat16 g_A_hi[(long long)NMAX * DMAX];
static __device__ __nv_bfloat16 g_A_lo[(long long)NMAX * DMAX];
static __device__ __nv_bfloat16 g_W1_hi[2048 * 256],   g_W1_lo[2048 * 256];
static __device__ __nv_bfloat16 g_W2l_hi[2048 * 2048], g_W2l_lo[2048 * 2048];
static __device__ __nv_bfloat16 g_W2r_hi[2048 * 2048], g_W2r_lo[2048 * 2048];
static __device__ __nv_bfloat16 g_W3l_hi[1024 * 2048], g_W3l_lo[1024 * 2048];
static __device__ __nv_bfloat16 g_W3r_hi[1024 * 2048], g_W3r_lo[1024 * 2048];

// ---------------- small PTX helpers (all sm_80-legal) -----------------------
__device__ __forceinline__ uint32_t smem_u32(const void* p) {
    uint32_t a;
    asm("{ .reg .u64 t; cvta.to.shared.u64 t, %1; cvt.u32.u64 %0, t; }" : "=r"(a) : "l"(p));
    return a;
}
#define CP_ASYNC16(dst, src) \
    asm volatile("cp.async.cg.shared.global [%0], [%1], 16;" :: "r"(dst), "l"(src) : "memory")
#define CP_COMMIT() asm volatile("cp.async.commit_group;" ::: "memory")
#define CP_WAIT(n)  asm volatile("cp.async.wait_group %0;" :: "n"(n) : "memory")
#define LDSM4(r, a)                                                                   \
    asm volatile("ldmatrix.sync.aligned.m8n8.x4.shared.b16 {%0,%1,%2,%3}, [%4];"      \
        : "=r"((r)[0]), "=r"((r)[1]), "=r"((r)[2]), "=r"((r)[3]) : "r"(a))
__device__ __forceinline__ void mma16816(float* c, const uint32_t* a, const uint32_t* b) {
    asm volatile(
        "mma.sync.aligned.m16n8k16.row.col.f32.bf16.bf16.f32 "
        "{%0,%1,%2,%3}, {%4,%5,%6,%7}, {%8,%9}, {%0,%1,%2,%3};"
        : "+f"(c[0]), "+f"(c[1]), "+f"(c[2]), "+f"(c[3])
        : "r"(a[0]), "r"(a[1]), "r"(a[2]), "r"(a[3]), "r"(b[0]), "r"(b[1]));
}

// ---------------- edge utils (proven R1) ------------------------------------
__global__ void detect_dtype_kernel(const int* __restrict__ w, int n) {
    __shared__ int f;
    if (threadIdx.x == 0) f = 0;
    __syncthreads();
    for (int i = threadIdx.x; i < n; i += blockDim.x)
        if (w[2 * i + 1] != 0) f = 1;
    __syncthreads();
    if (threadIdx.x == 0) g_is64 = f ? 0 : 1;
}
__device__ __forceinline__ int edge_at(const void* ei, long long i, int is64) {
    return is64 ? (int)((const long long*)ei)[i] : ((const int*)ei)[i];
}
__global__ void count_deg_kernel(const void* __restrict__ ei, int E) {
    int e = blockIdx.x * blockDim.x + threadIdx.x;
    if (e >= E) return;
    atomicAdd(&g_cnt[edge_at(ei, (long long)E + e, g_is64)], 1.0f);
}
__global__ void inv_cnt_kernel(int N) {
    int i = blockIdx.x * blockDim.x + threadIdx.x;
    if (i < N) g_invcnt[i] = 1.0f / fmaxf(g_cnt[i], 1.0f);
}
__global__ void scatter_add_kernel(const float* __restrict__ S, const void* __restrict__ ei,
                                   float* __restrict__ AGG, int E, int D) {
    const int gw = (blockIdx.x * blockDim.x + threadIdx.x) >> 5;
    const int lane = threadIdx.x & 31;
    if (gw >= E) return;
    const int is64 = g_is64;
    const int s = edge_at(ei, gw, is64);
    const int d = edge_at(ei, (long long)E + gw, is64);
    const float4* sr = (const float4*)(S + (long long)s * D);
    float* dr = AGG + (long long)d * D;
    const int n4 = D >> 2;
    for (int c = lane; c < n4; c += 32) {
        float4 v = sr[c];
        atomicAdd(dr + 4 * c + 0, v.x);
        atomicAdd(dr + 4 * c + 1, v.y);
        atomicAdd(dr + 4 * c + 2, v.z);
        atomicAdd(dr + 4 * c + 3, v.w);
    }
}

// ---------------- conversions ----------------------------------------------
__device__ __forceinline__ void split1(float f, __nv_bfloat16& h, __nv_bfloat16& l) {
    h = __float2bfloat16(f);
    l = __float2bfloat16(f - __bfloat162float(h));
}
__global__ void split_kernel(const float* __restrict__ s, __nv_bfloat16* __restrict__ hi,
                             __nv_bfloat16* __restrict__ lo, long long n4) {
    long long i = (long long)blockIdx.x * blockDim.x + threadIdx.x;
    if (i >= n4) return;
    float4 v = ((const float4*)s)[i];
    __nv_bfloat16 h0, l0, h1, l1, h2, l2, h3, l3;
    split1(v.x, h0, l0); split1(v.y, h1, l1); split1(v.z, h2, l2); split1(v.w, h3, l3);
    __nv_bfloat162* H = (__nv_bfloat162*)hi;
    __nv_bfloat162* L = (__nv_bfloat162*)lo;
    H[2 * i]     = __nv_bfloat162(h0, h1);
    H[2 * i + 1] = __nv_bfloat162(h2, h3);
    L[2 * i]     = __nv_bfloat162(l0, l1);
    L[2 * i + 1] = __nv_bfloat162(l2, l3);
}
// X[r, 0..127] = AGG[r,:] * invcnt[r];  X[r, 128..255] = x[r,:]
__global__ void xcat_kernel(const float* __restrict__ x, int N) {
    long long i = (long long)blockIdx.x * blockDim.x + threadIdx.x;
    if (i >= (long long)N * 256) return;
    int r = (int)(i >> 8), c = (int)(i & 255);
    float f = (c < 128) ? g_AGG[(long long)r * 128 + c] * g_invcnt[r]
                        : x[(long long)r * 128 + (c - 128)];
    __nv_bfloat16 h, l;
    split1(f, h, l);
    g_X_hi[i] = h;
    g_X_lo[i] = l;
}
// W[K,N] f32 -> T[n][kofs + k] hi/lo bf16 (row stride ldT), tiled transpose
__global__ void wsplitT_kernel(const float* __restrict__ W, __nv_bfloat16* __restrict__ Th,
                               __nv_bfloat16* __restrict__ Tl, int K, int N, int ldT, int kofs) {
    __shared__ float t[32][33];
    int n0 = blockIdx.x * 32, k0 = blockIdx.y * 32;
    for (int dy = threadIdx.y; dy < 32; dy += 8)
        t[dy][threadIdx.x] = W[(long long)(k0 + dy) * N + n0 + threadIdx.x];
    __syncthreads();
    for (int dy = threadIdx.y; dy < 32; dy += 8) {
        int n = n0 + dy, k = k0 + threadIdx.x;
        __nv_bfloat16 h, l;
        split1(t[threadIdx.x][dy], h, l);
        Th[(long long)n * ldT + kofs + k] = h;
        Tl[(long long)n * ldT + kofs + k] = l;
    }
}

// ---------------- mma.sync GEMM ---------------------------------------------
// C[M,Nc] = act( Ahi@Bhi^T + Ahi@Blo^T + Alo@Bhi^T + addmat*rowscale + bias )
// A: [M,K] hi/lo bf16 row-major; B: [Nc,K] hi/lo bf16 row-major.
// CTA tile 128x128, BK=64, 3-stage cp.async, 8 warps (2 M x 4 N), warp 64x32.
#define STG        3
#define STAGE_BY   65536              // Ah 16K | Al 16K | Bh 16K | Bl 16K
#define SMEM_TOT   (STG * STAGE_BY)   // 192 KB

__global__ __launch_bounds__(256, 1)
void mma_gemm(const __nv_bfloat16* __restrict__ Ah, const __nv_bfloat16* __restrict__ Al,
              const __nv_bfloat16* __restrict__ Bh, const __nv_bfloat16* __restrict__ Bl,
              float* __restrict__ C, const float* __restrict__ addmat,
              const float* __restrict__ rowscale, const float* __restrict__ bias,
              int M, int Nc, int K, int relu) {
    extern __shared__ char sm[];
    const uint32_t sb = smem_u32(sm);
    const int tid = threadIdx.x, wid = tid >> 5, lane = tid & 31;
    const int m0 = blockIdx.y * 128, n0 = blockIdx.x * 128;
    const int nk = K >> 6;

    // ---- cp.async mapping: thread -> (row, 4 of 8 16B-units) ----
    const int lrow = tid >> 1;
    const int u0   = (tid & 1) * 4;
    const bool arow_ok = (m0 + lrow) < M;
    const __nv_bfloat16* gAh = Ah + (long long)(m0 + lrow) * K;
    const __nv_bfloat16* gAl = Al + (long long)(m0 + lrow) * K;
    const __nv_bfloat16* gBh = Bh + (long long)(n0 + lrow) * K;
    const __nv_bfloat16* gBl = Bl + (long long)(n0 + lrow) * K;
    uint32_t sst[4];
#pragma unroll
    for (int j = 0; j < 4; j++) {
        int u = u0 + j;
        sst[j] = lrow * 128 + ((u ^ (lrow & 7)) * 16);
    }

    float acc[4][4][4];
#pragma unroll
    for (int a = 0; a < 4; a++)
#pragma unroll
        for (int b = 0; b < 4; b++)
#pragma unroll
            for (int c = 0; c < 4; c++) acc[a][b][c] = 0.f;

    const int m0w = (wid & 1) * 64, n0w = (wid >> 1) * 32;

    // ---- issue stage kt ----
    auto issue = [&](int kt) {
        const uint32_t base = sb + (kt % STG) * STAGE_BY;
        const int k0 = kt * 64;
#pragma unroll
        for (int j = 0; j < 4; j++) {
            const int u = u0 + j;
            if (arow_ok) {
                CP_ASYNC16(base + sst[j],         gAh + k0 + u * 8);
                CP_ASYNC16(base + 16384 + sst[j], gAl + k0 + u * 8);
            }
            CP_ASYNC16(base + 32768 + sst[j], gBh + k0 + u * 8);
            CP_ASYNC16(base + 49152 + sst[j], gBl + k0 + u * 8);
        }
        CP_COMMIT();
    };

    const int pro = nk < STG ? nk : STG;
    for (int p = 0; p < pro; p++) issue(p);

    for (int kt = 0; kt < nk; kt++) {
        const int pend = min(nk - 1 - kt, STG - 1);
        if (pend >= 2) CP_WAIT(2);
        else if (pend == 1) CP_WAIT(1);
        else CP_WAIT(0);
        __syncthreads();

        const uint32_t Ab = sb + (kt % STG) * STAGE_BY;
#pragma unroll
        for (int ks = 0; ks < 4; ks++) {
            uint32_t afh[4][4], afl[4][4];
#pragma unroll
            for (int mc = 0; mc < 4; mc++) {
                const int r = m0w + mc * 16 + (lane & 15);
                const int u = ks * 2 + (lane >> 4);
                const uint32_t ad = Ab + r * 128 + ((u ^ (r & 7)) * 16);
                LDSM4(afh[mc], ad);
                LDSM4(afl[mc], ad + 16384);
            }
            uint32_t bfh[2][4], bfl[2][4];
#pragma unroll
            for (int pr = 0; pr < 2; pr++) {
                const int n = n0w + pr * 16 + ((lane >> 4) & 1) * 8 + (lane & 7);
                const int u = ks * 2 + ((lane >> 3) & 1);
                const uint32_t bd = Ab + 32768 + n * 128 + ((u ^ (n & 7)) * 16);
                LDSM4(bfh[pr], bd);
                LDSM4(bfl[pr], bd + 16384);
            }
#pragma unroll
            for (int mc = 0; mc < 4; mc++)
#pragma unroll
                for (int pr = 0; pr < 2; pr++)
#pragma unroll
                    for (int h = 0; h < 2; h++) {
                        const int nc = pr * 2 + h;
                        mma16816(acc[mc][nc], afh[mc], &bfh[pr][h * 2]);
                        mma16816(acc[mc][nc], afh[mc], &bfl[pr][h * 2]);
                        mma16816(acc[mc][nc], afl[mc], &bfh[pr][h * 2]);
                    }
        }
        __syncthreads();
        if (kt + STG < nk) issue(kt + STG);
    }

    // ---- fused epilogue ----
#pragma unroll
    for (int mc = 0; mc < 4; mc++) {
        const int r0 = m0 + m0w + mc * 16 + (lane >> 2);
        const int r1 = r0 + 8;
        const float rs0 = (rowscale && r0 < M) ? rowscale[r0] : 0.f;
        const float rs1 = (rowscale && r1 < M) ? rowscale[r1] : 0.f;
#pragma unroll
        for (int nc = 0; nc < 4; nc++) {
            const int col = n0 + n0w + nc * 8 + (lane & 3) * 2;
            float2 bv = make_float2(0.f, 0.f);
            if (bias) bv = *(const float2*)(bias + col);
            if (r0 < M) {
                float2 v = make_float2(acc[mc][nc][0], acc[mc][nc][1]);
                if (addmat) {
                    float2 a = *(const float2*)(addmat + (long long)r0 * Nc + col);
                    v.x += a.x * rs0; v.y += a.y * rs0;
                }
                v.x += bv.x; v.y += bv.y;
                if (relu) { v.x = fmaxf(v.x, 0.f); v.y = fmaxf(v.y, 0.f); }
                *(float2*)(C + (long long)r0 * Nc + col) = v;
            }
            if (r1 < M) {
                float2 v = make_float2(acc[mc][nc][2], acc[mc][nc][3]);
                if (addmat) {
                    float2 a = *(const float2*)(addmat + (long long)r1 * Nc + col);
                    v.x += a.x * rs1; v.y += a.y * rs1;
                }
                v.x += bv.x; v.y += bv.y;
                if (relu) { v.x = fmaxf(v.x, 0.f); v.y = fmaxf(v.y, 0.f); }
                *(float2*)(C + (long long)r1 * Nc + col) = v;
            }
        }
    }
}

// ---------------- L2 normalize (D3 = 1024) ----------------------------------
__global__ void l2norm_kernel(const float* __restrict__ H, float* __restrict__ out) {
    const int row = blockIdx.x;
    const float4* h = (const float4*)H + (long long)row * 256;
    float4 v = h[threadIdx.x];
    float s = v.x * v.x + v.y * v.y + v.z * v.z + v.w * v.w;
#pragma unroll
    for (int o = 16; o; o >>= 1) s += __shfl_xor_sync(0xFFFFFFFFu, s, o);
    __shared__ float ws[8];
    if ((threadIdx.x & 31) == 0) ws[threadIdx.x >> 5] = s;
    __syncthreads();
    if (threadIdx.x < 8) {
        float t = ws[threadIdx.x];
#pragma unroll
        for (int o = 4; o; o >>= 1) t += __shfl_xor_sync(0xFFu, t, o);
        if (threadIdx.x == 0) ws[0] = t;
    }
    __syncthreads();
    const float inv = 1.0f / fmaxf(sqrtf(ws[0]), 1e-12f);
    ((float4*)out)[(long long)row * 256 + threadIdx.x] =
        make_float4(v.x * inv, v.y * inv, v.z * inv, v.w * inv);
}

// ---------------- host ------------------------------------------------------
static void run_mma(const __nv_bfloat16* Ah, const __nv_bfloat16* Al,
                    const __nv_bfloat16* Bh, const __nv_bfloat16* Bl,
                    float* C, const float* addmat, const float* rowscale,
                    const float* bias, int M, int Nc, int K, int relu) {
    static bool attr_set = false;
    if (!attr_set) {
        cudaFuncSetAttribute(mma_gemm, cudaFuncAttributeMaxDynamicSharedMemorySize, SMEM_TOT);
        attr_set = true;
    }
    dim3 grid(Nc / 128, (M + 127) / 128);
    mma_gemm<<<grid, 256, SMEM_TOT>>>(Ah, Al, Bh, Bl, C, addmat, rowscale, bias, M, Nc, K, relu);
}

extern "C" void kernel_launch(void* const* d_in, const int* in_sizes, int n_in,
                              void* d_out, int out_size) {
    const float* x   = (const float*)d_in[0];
    const void*  ei  = d_in[2];
    const float* W1l = (const float*)d_in[3];
    const float* W1r = (const float*)d_in[4];
    const float* b1  = (const float*)d_in[5];
    const float* W2l = (const float*)d_in[6];
    const float* W2r = (const float*)d_in[7];
    const float* b2  = (const float*)d_in[8];
    const float* W3l = (const float*)d_in[9];
    const float* W3r = (const float*)d_in[10];
    const float* b3  = (const float*)d_in[11];

    const int D1 = in_sizes[5];       // 2048
    const int D2 = in_sizes[8];       // 2048
    const int D3 = in_sizes[11];      // 1024
    const int F  = in_sizes[3] / D1;  // 128
    const int N  = in_sizes[0] / F;   // 50000
    const int E  = in_sizes[2] / 2;   // 400000

    float *P, *AGG, *H, *cnt, *invc;
    cudaGetSymbolAddress((void**)&P, g_P);
    cudaGetSymbolAddress((void**)&AGG, g_AGG);
    cudaGetSymbolAddress((void**)&H, g_H);
    cudaGetSymbolAddress((void**)&cnt, g_cnt);
    cudaGetSymbolAddress((void**)&invc, g_invcnt);
    __nv_bfloat16 *Ahp, *Alp, *Xh, *Xl, *W1h, *W1lo, *W2lh, *W2ll, *W2rh, *W2rl,
                  *W3lh, *W3ll, *W3rh, *W3rl;
    cudaGetSymbolAddress((void**)&Ahp, g_A_hi);
    cudaGetSymbolAddress((void**)&Alp, g_A_lo);
    cudaGetSymbolAddress((void**)&Xh, g_X_hi);
    cudaGetSymbolAddress((void**)&Xl, g_X_lo);
    cudaGetSymbolAddress((void**)&W1h, g_W1_hi);
    cudaGetSymbolAddress((void**)&W1lo, g_W1_lo);
    cudaGetSymbolAddress((void**)&W2lh, g_W2l_hi);
    cudaGetSymbolAddress((void**)&W2ll, g_W2l_lo);
    cudaGetSymbolAddress((void**)&W2rh, g_W2r_hi);
    cudaGetSymbolAddress((void**)&W2rl, g_W2r_lo);
    cudaGetSymbolAddress((void**)&W3lh, g_W3l_hi);
    cudaGetSymbolAddress((void**)&W3ll, g_W3l_lo);
    cudaGetSymbolAddress((void**)&W3rh, g_W3r_hi);
    cudaGetSymbolAddress((void**)&W3rl, g_W3r_lo);

    float* out = (float*)d_out;
    const int TPB = 256;
    const int eb = (E + TPB - 1) / TPB;
    const int wb = (E * 32 + TPB - 1) / TPB;

    // prologue: dtype sniff, degrees, layer-1 x aggregation
    detect_dtype_kernel<<<1, 256>>>((const int*)ei, E < 1024 ? E : 1024);
    cudaMemsetAsync(cnt, 0, (size_t)N * sizeof(float));
    count_deg_kernel<<<eb, TPB>>>(ei, E);
    inv_cnt_kernel<<<(N + TPB - 1) / TPB, TPB>>>(N);
    cudaMemsetAsync(AGG, 0, (size_t)N * F * sizeof(float));
    scatter_add_kernel<<<wb, TPB>>>(x, ei, AGG, E, F);

    // weight transpose+split: W[K,N] -> T[n][k] hi/lo
    dim3 tb(32, 8);
    wsplitT_kernel<<<dim3(D1 / 32, F / 32), tb>>>(W1l, W1h, W1lo, F, D1, 2 * F, 0);
    wsplitT_kernel<<<dim3(D1 / 32, F / 32), tb>>>(W1r, W1h, W1lo, F, D1, 2 * F, F);
    wsplitT_kernel<<<dim3(D2 / 32, D1 / 32), tb>>>(W2l, W2lh, W2ll, D1, D2, D1, 0);
    wsplitT_kernel<<<dim3(D2 / 32, D1 / 32), tb>>>(W2r, W2rh, W2rl, D1, D2, D1, 0);
    wsplitT_kernel<<<dim3(D3 / 32, D2 / 32), tb>>>(W3l, W3lh, W3ll, D2, D3, D2, 0);
    wsplitT_kernel<<<dim3(D3 / 32, D2 / 32), tb>>>(W3r, W3rh, W3rl, D2, D3, D2, 0);

    // ---- layer 1: X = [mean_x | x] hi/lo, one GEMM with K = 256 ----
    {
        long long tot = (long long)N * 256;
        xcat_kernel<<<(int)((tot + TPB - 1) / TPB), TPB>>>(x, N);
    }
    run_mma(Xh, Xl, W1h, W1lo, H, nullptr, nullptr, b1, N, D1, 2 * F, 1);

    // ---- layer 2 ----
    {
        long long n4 = (long long)N * D1 / 4;
        split_kernel<<<(int)((n4 + TPB - 1) / TPB), TPB>>>(H, Ahp, Alp, n4);
    }
    run_mma(Ahp, Alp, W2lh, W2ll, P, nullptr, nullptr, nullptr, N, D2, D1, 0);
    cudaMemsetAsync(AGG, 0, (size_t)N * D2 * sizeof(float));
    scatter_add_kernel<<<wb, TPB>>>(P, ei, AGG, E, D2);
    run_mma(Ahp, Alp, W2rh, W2rl, H, AGG, invc, b2, N, D2, D1, 1);

    // ---- layer 3 ----
    {
        long long n4 = (long long)N * D2 / 4;
        split_kernel<<<(int)((n4 + TPB - 1) / TPB), TPB>>>(H, Ahp, Alp, n4);
    }
    run_mma(Ahp, Alp, W3lh, W3ll, P, nullptr, nullptr, nullptr, N, D3, D2, 0);
    cudaMemsetAsync(AGG, 0, (size_t)N * D3 * sizeof(float));
    scatter_add_kernel<<<wb, TPB>>>(P, ei, AGG, E, D3);
    run_mma(Ahp, Alp, W3rh, W3rl, H, AGG, invc, b3, N, D3, D2, 1);

    // ---- normalize ----
    l2norm_kernel<<<N, 256>>>(H, out);
    (void)n_in; (void)out_size;
}

// round 5
// speedup vs baseline: 2.4533x; 1.2327x over previous
#include <cuda_runtime.h>
#include <cuda_bf16.h>
#include <cstdint>

// ===========================================================================
// GraphSAGE 3-layer forward, plain sm_100 target.
// R5 = R4 (single-sync cp.async pipeline, CSR gather, fused split epilogue)
// with A2 buffers ALIASED onto g_P to keep device statics < 2 GB (R4 link fail).
// ===========================================================================

#define NMAX 50000
#define DMAX 2048
#define EMAX 450000

static __device__ float g_P  [(long long)NMAX * DMAX];   // f32 scratch; aliased as A2 bf16 hi/lo
static __device__ float g_AGG[(long long)NMAX * DMAX];
static __device__ float g_H  [(long long)NMAX * DMAX];   // layer-3 P and final H3
static __device__ int   g_cnt_i [NMAX];
static __device__ float g_invcnt[NMAX];
static __device__ int   g_rowptr[NMAX + 1];
static __device__ int   g_cursor[NMAX];
static __device__ int   g_csr   [EMAX];
static __device__ int   g_is64;

static __device__ __nv_bfloat16 g_X_hi[(long long)NMAX * 256];
static __device__ __nv_bfloat16 g_X_lo[(long long)NMAX * 256];
static __device__ __nv_bfloat16 g_A1_hi[(long long)NMAX * DMAX];
static __device__ __nv_bfloat16 g_A1_lo[(long long)NMAX * DMAX];
static __device__ __nv_bfloat16 g_W1_hi[2048 * 256],   g_W1_lo[2048 * 256];
static __device__ __nv_bfloat16 g_W2l_hi[2048 * 2048], g_W2l_lo[2048 * 2048];
static __device__ __nv_bfloat16 g_W2r_hi[2048 * 2048], g_W2r_lo[2048 * 2048];
static __device__ __nv_bfloat16 g_W3l_hi[1024 * 2048], g_W3l_lo[1024 * 2048];
static __device__ __nv_bfloat16 g_W3r_hi[1024 * 2048], g_W3r_lo[1024 * 2048];

// ---------------- PTX helpers (sm_80-legal only) -----------------------------
__device__ __forceinline__ uint32_t smem_u32(const void* p) {
    uint32_t a;
    asm("{ .reg .u64 t; cvta.to.shared.u64 t, %1; cvt.u32.u64 %0, t; }" : "=r"(a) : "l"(p));
    return a;
}
#define CP_ASYNC16(dst, src) \
    asm volatile("cp.async.cg.shared.global [%0], [%1], 16;" :: "r"(dst), "l"(src) : "memory")
#define CP_COMMIT() asm volatile("cp.async.commit_group;" ::: "memory")
#define CP_WAIT(n)  asm volatile("cp.async.wait_group %0;" :: "n"(n) : "memory")
#define LDSM4(r, a)                                                                   \
    asm volatile("ldmatrix.sync.aligned.m8n8.x4.shared.b16 {%0,%1,%2,%3}, [%4];"      \
        : "=r"((r)[0]), "=r"((r)[1]), "=r"((r)[2]), "=r"((r)[3]) : "r"(a))
__device__ __forceinline__ void mma16816(float* c, const uint32_t* a, const uint32_t* b) {
    asm volatile(
        "mma.sync.aligned.m16n8k16.row.col.f32.bf16.bf16.f32 "
        "{%0,%1,%2,%3}, {%4,%5,%6,%7}, {%8,%9}, {%0,%1,%2,%3};"
        : "+f"(c[0]), "+f"(c[1]), "+f"(c[2]), "+f"(c[3])
        : "r"(a[0]), "r"(a[1]), "r"(a[2]), "r"(a[3]), "r"(b[0]), "r"(b[1]));
}

// ---------------- edge / CSR utils -------------------------------------------
__global__ void detect_dtype_kernel(const int* __restrict__ w, int n) {
    __shared__ int f;
    if (threadIdx.x == 0) f = 0;
    __syncthreads();
    for (int i = threadIdx.x; i < n; i += blockDim.x)
        if (w[2 * i + 1] != 0) f = 1;
    __syncthreads();
    if (threadIdx.x == 0) g_is64 = f ? 0 : 1;
}
__device__ __forceinline__ int edge_at(const void* ei, long long i, int is64) {
    return is64 ? (int)((const long long*)ei)[i] : ((const int*)ei)[i];
}
__global__ void count_deg_kernel(const void* __restrict__ ei, int E) {
    int e = blockIdx.x * blockDim.x + threadIdx.x;
    if (e >= E) return;
    atomicAdd(&g_cnt_i[edge_at(ei, (long long)E + e, g_is64)], 1);
}
__global__ void inv_cnt_kernel(int N) {
    int i = blockIdx.x * blockDim.x + threadIdx.x;
    if (i < N) g_invcnt[i] = 1.0f / (float)max(g_cnt_i[i], 1);
}
// single-block exclusive scan of g_cnt_i -> g_rowptr / g_cursor
__global__ void scan_kernel(int N) {
    __shared__ int smv[1024];
    __shared__ int carry;
    const int tid = threadIdx.x;
    if (tid == 0) carry = 0;
    __syncthreads();
    for (int base = 0; base < N; base += 1024) {
        int v = (base + tid < N) ? g_cnt_i[base + tid] : 0;
        smv[tid] = v;
        __syncthreads();
        for (int off = 1; off < 1024; off <<= 1) {
            int t = (tid >= off) ? smv[tid - off] : 0;
            __syncthreads();
            smv[tid] += t;
            __syncthreads();
        }
        const int excl = smv[tid] - v + carry;
        if (base + tid < N) { g_rowptr[base + tid] = excl; g_cursor[base + tid] = excl; }
        const int tot = smv[1023];
        __syncthreads();
        if (tid == 0) carry += tot;
        __syncthreads();
    }
    if (tid == 0) g_rowptr[N] = carry;
}
__global__ void fill_csr_kernel(const void* __restrict__ ei, int E) {
    int e = blockIdx.x * blockDim.x + threadIdx.x;
    if (e >= E) return;
    const int is64 = g_is64;
    const int s = edge_at(ei, e, is64);
    const int d = edge_at(ei, (long long)E + e, is64);
    g_csr[atomicAdd(&g_cursor[d], 1)] = s;
}
// AGG[node,:] = sum_{src in neigh(node)} S[src,:]  (raw sum; mean scale later)
__global__ void gather_sum_kernel(const float* __restrict__ S, float* __restrict__ AGG, int D) {
    const int node = blockIdx.x;
    const int col = blockIdx.y * 512 + threadIdx.x * 4;
    if (col >= D) return;
    const int beg = g_rowptr[node], end = g_rowptr[node + 1];
    float4 acc = make_float4(0.f, 0.f, 0.f, 0.f);
    for (int i = beg; i < end; i++) {
        const float4 v = *(const float4*)(S + (long long)g_csr[i] * D + col);
        acc.x += v.x; acc.y += v.y; acc.z += v.z; acc.w += v.w;
    }
    *(float4*)(AGG + (long long)node * D + col) = acc;
}

// ---------------- conversions ------------------------------------------------
__device__ __forceinline__ void split1(float f, __nv_bfloat16& h, __nv_bfloat16& l) {
    h = __float2bfloat16(f);
    l = __float2bfloat16(f - __bfloat162float(h));
}
// X[r,0..127] = AGG[r,:]*invcnt[r]; X[r,128..255] = x[r,:]  (hi/lo)
__global__ void xcat_kernel(const float* __restrict__ x, int N) {
    long long i = (long long)blockIdx.x * blockDim.x + threadIdx.x;
    if (i >= (long long)N * 256) return;
    int r = (int)(i >> 8), c = (int)(i & 255);
    float f = (c < 128) ? g_AGG[(long long)r * 128 + c] * g_invcnt[r]
                        : x[(long long)r * 128 + (c - 128)];
    __nv_bfloat16 h, l;
    split1(f, h, l);
    g_X_hi[i] = h;
    g_X_lo[i] = l;
}
// W[K,N] f32 -> T[n][kofs+k] hi/lo bf16 (row stride ldT)
__global__ void wsplitT_kernel(const float* __restrict__ W, __nv_bfloat16* __restrict__ Th,
                               __nv_bfloat16* __restrict__ Tl, int K, int N, int ldT, int kofs) {
    __shared__ float t[32][33];
    int n0 = blockIdx.x * 32, k0 = blockIdx.y * 32;
    for (int dy = threadIdx.y; dy < 32; dy += 8)
        t[dy][threadIdx.x] = W[(long long)(k0 + dy) * N + n0 + threadIdx.x];
    __syncthreads();
    for (int dy = threadIdx.y; dy < 32; dy += 8) {
        int n = n0 + dy, k = k0 + threadIdx.x;
        __nv_bfloat16 h, l;
        split1(t[threadIdx.x][dy], h, l);
        Th[(long long)n * ldT + kofs + k] = h;
        Tl[(long long)n * ldT + kofs + k] = l;
    }
}

// ---------------- mma.sync GEMM ----------------------------------------------
// D = act(Ahi@Bhi^T + Ahi@Blo^T + Alo@Bhi^T + addmat*rowscale + bias)
// writes: C (f32, optional) and/or Oh/Ol (bf16 hi/lo split, optional)
#define STG        3
#define STAGE_BY   65536
#define SMEM_TOT   (STG * STAGE_BY)

__global__ __launch_bounds__(256, 1)
void mma_gemm(const __nv_bfloat16* __restrict__ Ah, const __nv_bfloat16* __restrict__ Al,
              const __nv_bfloat16* __restrict__ Bh, const __nv_bfloat16* __restrict__ Bl,
              float* __restrict__ C,
              __nv_bfloat16* __restrict__ Oh, __nv_bfloat16* __restrict__ Ol,
              const float* __restrict__ addmat, const float* __restrict__ rowscale,
              const float* __restrict__ bias, int M, int Nc, int K, int relu) {
    extern __shared__ char sm[];
    const uint32_t sb = smem_u32(sm);
    const int tid = threadIdx.x, wid = tid >> 5, lane = tid & 31;
    const int m0 = blockIdx.y * 128, n0 = blockIdx.x * 128;
    const int nk = K >> 6;

    const int lrow = tid >> 1;
    const int u0   = (tid & 1) * 4;
    const bool arow_ok = (m0 + lrow) < M;
    const __nv_bfloat16* gAh = Ah + (long long)(m0 + lrow) * K;
    const __nv_bfloat16* gAl = Al + (long long)(m0 + lrow) * K;
    const __nv_bfloat16* gBh = Bh + (long long)(n0 + lrow) * K;
    const __nv_bfloat16* gBl = Bl + (long long)(n0 + lrow) * K;
    uint32_t sst[4];
#pragma unroll
    for (int j = 0; j < 4; j++) {
        int u = u0 + j;
        sst[j] = lrow * 128 + ((u ^ (lrow & 7)) * 16);
    }

    float acc[4][4][4];
#pragma unroll
    for (int a = 0; a < 4; a++)
#pragma unroll
        for (int b = 0; b < 4; b++)
#pragma unroll
            for (int c = 0; c < 4; c++) acc[a][b][c] = 0.f;

    const int m0w = (wid & 1) * 64, n0w = (wid >> 1) * 32;

    auto issue = [&](int kt) {
        const uint32_t base = sb + (kt % STG) * STAGE_BY;
        const int k0 = kt * 64;
#pragma unroll
        for (int j = 0; j < 4; j++) {
            const int u = u0 + j;
            if (arow_ok) {
                CP_ASYNC16(base + sst[j],         gAh + k0 + u * 8);
                CP_ASYNC16(base + 16384 + sst[j], gAl + k0 + u * 8);
            }
            CP_ASYNC16(base + 32768 + sst[j], gBh + k0 + u * 8);
            CP_ASYNC16(base + 49152 + sst[j], gBl + k0 + u * 8);
        }
        CP_COMMIT();
    };

    const int pro = nk < 2 ? nk : 2;
    for (int p = 0; p < pro; p++) issue(p);

    for (int kt = 0; kt < nk; kt++) {
        if (kt + 1 < nk) CP_WAIT(1);
        else             CP_WAIT(0);
        __syncthreads();                 // all warps done reading slot (kt-1)%3
        if (kt + 2 < nk) issue(kt + 2);  // refill that slot, overlapped w/ compute

        const uint32_t Ab = sb + (kt % STG) * STAGE_BY;
#pragma unroll
        for (int ks = 0; ks < 4; ks++) {
            uint32_t afh[4][4], afl[4][4];
#pragma unroll
            for (int mc = 0; mc < 4; mc++) {
                const int r = m0w + mc * 16 + (lane & 15);
                const int u = ks * 2 + (lane >> 4);
                const uint32_t ad = Ab + r * 128 + ((u ^ (r & 7)) * 16);
                LDSM4(afh[mc], ad);
                LDSM4(afl[mc], ad + 16384);
            }
            uint32_t bfh[2][4], bfl[2][4];
#pragma unroll
            for (int pr = 0; pr < 2; pr++) {
                const int n = n0w + pr * 16 + ((lane >> 4) & 1) * 8 + (lane & 7);
                const int u = ks * 2 + ((lane >> 3) & 1);
                const uint32_t bd = Ab + 32768 + n * 128 + ((u ^ (n & 7)) * 16);
                LDSM4(bfh[pr], bd);
                LDSM4(bfl[pr], bd + 16384);
            }
#pragma unroll
            for (int mc = 0; mc < 4; mc++)
#pragma unroll
                for (int pr = 0; pr < 2; pr++)
#pragma unroll
                    for (int h = 0; h < 2; h++) {
                        const int nc = pr * 2 + h;
                        mma16816(acc[mc][nc], afh[mc], &bfh[pr][h * 2]);
                        mma16816(acc[mc][nc], afh[mc], &bfl[pr][h * 2]);
                        mma16816(acc[mc][nc], afl[mc], &bfh[pr][h * 2]);
                    }
        }
    }

    // ---- fused epilogue ----
#pragma unroll
    for (int mc = 0; mc < 4; mc++) {
        const int r0 = m0 + m0w + mc * 16 + (lane >> 2);
        const int r1 = r0 + 8;
        const float rs0 = (rowscale && r0 < M) ? rowscale[r0] : 0.f;
        const float rs1 = (rowscale && r1 < M) ? rowscale[r1] : 0.f;
#pragma unroll
        for (int nc = 0; nc < 4; nc++) {
            const int col = n0 + n0w + nc * 8 + (lane & 3) * 2;
            float2 bv = make_float2(0.f, 0.f);
            if (bias) bv = *(const float2*)(bias + col);
#pragma unroll
            for (int half = 0; half < 2; half++) {
                const int r = half ? r1 : r0;
                if (r >= M) continue;
                const float rs = half ? rs1 : rs0;
                float2 v = make_float2(acc[mc][nc][2 * half], acc[mc][nc][2 * half + 1]);
                if (addmat) {
                    float2 a = *(const float2*)(addmat + (long long)r * Nc + col);
                    v.x += a.x * rs; v.y += a.y * rs;
                }
                v.x += bv.x; v.y += bv.y;
                if (relu) { v.x = fmaxf(v.x, 0.f); v.y = fmaxf(v.y, 0.f); }
                if (C) *(float2*)(C + (long long)r * Nc + col) = v;
                if (Oh) {
                    __nv_bfloat16 h0, l0, h1, l1;
                    split1(v.x, h0, l0);
                    split1(v.y, h1, l1);
                    *(__nv_bfloat162*)(Oh + (long long)r * Nc + col) = __nv_bfloat162(h0, h1);
                    *(__nv_bfloat162*)(Ol + (long long)r * Nc + col) = __nv_bfloat162(l0, l1);
                }
            }
        }
    }
}

// ---------------- L2 normalize (D3 = 1024) -----------------------------------
__global__ void l2norm_kernel(const float* __restrict__ H, float* __restrict__ out) {
    const int row = blockIdx.x;
    const float4* h = (const float4*)H + (long long)row * 256;
    float4 v = h[threadIdx.x];
    float s = v.x * v.x + v.y * v.y + v.z * v.z + v.w * v.w;
#pragma unroll
    for (int o = 16; o; o >>= 1) s += __shfl_xor_sync(0xFFFFFFFFu, s, o);
    __shared__ float ws[8];
    if ((threadIdx.x & 31) == 0) ws[threadIdx.x >> 5] = s;
    __syncthreads();
    if (threadIdx.x < 8) {
        float t = ws[threadIdx.x];
#pragma unroll
        for (int o = 4; o; o >>= 1) t += __shfl_xor_sync(0xFFu, t, o);
        if (threadIdx.x == 0) ws[0] = t;
    }
    __syncthreads();
    const float inv = 1.0f / fmaxf(sqrtf(ws[0]), 1e-12f);
    ((float4*)out)[(long long)row * 256 + threadIdx.x] =
        make_float4(v.x * inv, v.y * inv, v.z * inv, v.w * inv);
}

// ---------------- host -------------------------------------------------------
static void run_mma(const __nv_bfloat16* Ah, const __nv_bfloat16* Al,
                    const __nv_bfloat16* Bh, const __nv_bfloat16* Bl,
                    float* C, __nv_bfloat16* Oh, __nv_bfloat16* Ol,
                    const float* addmat, const float* rowscale,
                    const float* bias, int M, int Nc, int K, int relu) {
    static bool attr_set = false;
    if (!attr_set) {
        cudaFuncSetAttribute(mma_gemm, cudaFuncAttributeMaxDynamicSharedMemorySize, SMEM_TOT);
        attr_set = true;
    }
    dim3 grid(Nc / 128, (M + 127) / 128);
    mma_gemm<<<grid, 256, SMEM_TOT>>>(Ah, Al, Bh, Bl, C, Oh, Ol,
                                      addmat, rowscale, bias, M, Nc, K, relu);
}

extern "C" void kernel_launch(void* const* d_in, const int* in_sizes, int n_in,
                              void* d_out, int out_size) {
    const float* x   = (const float*)d_in[0];
    const void*  ei  = d_in[2];
    const float* W1l = (const float*)d_in[3];
    const float* W1r = (const float*)d_in[4];
    const float* b1  = (const float*)d_in[5];
    const float* W2l = (const float*)d_in[6];
    const float* W2r = (const float*)d_in[7];
    const float* b2  = (const float*)d_in[8];
    const float* W3l = (const float*)d_in[9];
    const float* W3r = (const float*)d_in[10];
    const float* b3  = (const float*)d_in[11];

    const int D1 = in_sizes[5];       // 2048
    const int D2 = in_sizes[8];       // 2048
    const int D3 = in_sizes[11];      // 1024
    const int F  = in_sizes[3] / D1;  // 128
    const int N  = in_sizes[0] / F;   // 50000
    const int E  = in_sizes[2] / 2;   // 400000

    float *P, *AGG, *H, *invc;
    int* cnt_i;
    cudaGetSymbolAddress((void**)&P, g_P);
    cudaGetSymbolAddress((void**)&AGG, g_AGG);
    cudaGetSymbolAddress((void**)&H, g_H);
    cudaGetSymbolAddress((void**)&cnt_i, g_cnt_i);
    cudaGetSymbolAddress((void**)&invc, g_invcnt);
    __nv_bfloat16 *A1h, *A1l, *Xh, *Xl, *W1h, *W1lo,
                  *W2lh, *W2ll, *W2rh, *W2rl, *W3lh, *W3ll, *W3rh, *W3rl;
    cudaGetSymbolAddress((void**)&A1h, g_A1_hi);
    cudaGetSymbolAddress((void**)&A1l, g_A1_lo);
    cudaGetSymbolAddress((void**)&Xh, g_X_hi);
    cudaGetSymbolAddress((void**)&Xl, g_X_lo);
    cudaGetSymbolAddress((void**)&W1h, g_W1_hi);
    cudaGetSymbolAddress((void**)&W1lo, g_W1_lo);
    cudaGetSymbolAddress((void**)&W2lh, g_W2l_hi);
    cudaGetSymbolAddress((void**)&W2ll, g_W2l_lo);
    cudaGetSymbolAddress((void**)&W2rh, g_W2r_hi);
    cudaGetSymbolAddress((void**)&W2rl, g_W2r_lo);
    cudaGetSymbolAddress((void**)&W3lh, g_W3l_hi);
    cudaGetSymbolAddress((void**)&W3ll, g_W3l_lo);
    cudaGetSymbolAddress((void**)&W3rh, g_W3r_hi);
    cudaGetSymbolAddress((void**)&W3rl, g_W3r_lo);

    // A2 (bf16 hi/lo) aliases g_P: P is dead after the layer-2 gather consumes it.
    __nv_bfloat16* A2h = (__nv_bfloat16*)P;
    __nv_bfloat16* A2l = A2h + (long long)N * D2;

    float* out = (float*)d_out;
    const int TPB = 256;
    const int eb = (E + TPB - 1) / TPB;

    // ---- edge structures: dtype sniff, degrees, CSR ----
    detect_dtype_kernel<<<1, 256>>>((const int*)ei, E < 1024 ? E : 1024);
    cudaMemsetAsync(cnt_i, 0, (size_t)N * sizeof(int));
    count_deg_kernel<<<eb, TPB>>>(ei, E);
    inv_cnt_kernel<<<(N + TPB - 1) / TPB, TPB>>>(N);
    scan_kernel<<<1, 1024>>>(N);
    fill_csr_kernel<<<eb, TPB>>>(ei, E);

    // ---- weight transpose+split ----
    dim3 tb(32, 8);
    wsplitT_kernel<<<dim3(D1 / 32, F / 32), tb>>>(W1l, W1h, W1lo, F, D1, 2 * F, 0);
    wsplitT_kernel<<<dim3(D1 / 32, F / 32), tb>>>(W1r, W1h, W1lo, F, D1, 2 * F, F);
    wsplitT_kernel<<<dim3(D2 / 32, D1 / 32), tb>>>(W2l, W2lh, W2ll, D1, D2, D1, 0);
    wsplitT_kernel<<<dim3(D2 / 32, D1 / 32), tb>>>(W2r, W2rh, W2rl, D1, D2, D1, 0);
    wsplitT_kernel<<<dim3(D3 / 32, D2 / 32), tb>>>(W3l, W3lh, W3ll, D2, D3, D2, 0);
    wsplitT_kernel<<<dim3(D3 / 32, D2 / 32), tb>>>(W3r, W3rh, W3rl, D2, D3, D2, 0);

    // ---- layer 1: AGG = sum x[src]; X = [AGG*invcnt | x] hi/lo; H1 -> A1 ----
    gather_sum_kernel<<<dim3(N, (F + 511) / 512), 128>>>(x, AGG, F);
    {
        long long tot = (long long)N * 256;
        xcat_kernel<<<(int)((tot + TPB - 1) / TPB), TPB>>>(x, N);
    }
    run_mma(Xh, Xl, W1h, W1lo, nullptr, A1h, A1l, nullptr, nullptr, b1, N, D1, 2 * F, 1);

    // ---- layer 2: P = H1@W2l; AGG = gather(P); H2 -> A2 (in P's memory) ----
    run_mma(A1h, A1l, W2lh, W2ll, P, nullptr, nullptr, nullptr, nullptr, nullptr, N, D2, D1, 0);
    gather_sum_kernel<<<dim3(N, (D2 + 511) / 512), 128>>>(P, AGG, D2);
    run_mma(A1h, A1l, W2rh, W2rl, nullptr, A2h, A2l, AGG, invc, b2, N, D2, D1, 1);

    // ---- layer 3: P3 (in H) = H2@W3l; AGG = gather(P3); H3 -> H ----
    run_mma(A2h, A2l, W3lh, W3ll, H, nullptr, nullptr, nullptr, nullptr, nullptr, N, D3, D2, 0);
    gather_sum_kernel<<<dim3(N, (D3 + 511) / 512), 128>>>(H, AGG, D3);
    run_mma(A2h, A2l, W3rh, W3rl, H, nullptr, nullptr, AGG, invc, b3, N, D3, D2, 1);

    // ---- normalize ----
    l2norm_kernel<<<N, 256>>>(H, out);
    (void)n_in; (void)out_size;
}

// round 6
// speedup vs baseline: 3.4144x; 1.3918x over previous
#include <cuda_runtime.h>
#include <cuda_fp16.h>
#include <cstdint>

// ===========================================================================
// GraphSAGE 3-layer forward, plain sm_100 target.
// R6: fp16 split, 2-product GEMM (A single fp16, W = hi+lo fp16):
//     C = A*Wh + A*Wl  (fp32 acc)  -> 2.62 TFLOP of HMMA vs 3.93 in R5.
// 4-stage cp.async pipeline (48 KB/stage), CSR gather, fused epilogues.
// ===========================================================================

#define NMAX 50000
#define DMAX 2048
#define EMAX 450000

static __device__ float g_P  [(long long)NMAX * DMAX];   // f32 scratch; later aliased as A2 (fp16)
static __device__ float g_AGG[(long long)NMAX * DMAX];
static __device__ float g_H  [(long long)NMAX * DMAX];
static __device__ int   g_cnt_i [NMAX];
static __device__ float g_invcnt[NMAX];
static __device__ int   g_rowptr[NMAX + 1];
static __device__ int   g_cursor[NMAX];
static __device__ int   g_csr   [EMAX];
static __device__ int   g_is64;

static __device__ __half g_Xh [(long long)NMAX * 256];
static __device__ __half g_A1h[(long long)NMAX * DMAX];
static __device__ __half g_W1_hi[2048 * 256],   g_W1_lo[2048 * 256];
static __device__ __half g_W2l_hi[2048 * 2048], g_W2l_lo[2048 * 2048];
static __device__ __half g_W2r_hi[2048 * 2048], g_W2r_lo[2048 * 2048];
static __device__ __half g_W3l_hi[1024 * 2048], g_W3l_lo[1024 * 2048];
static __device__ __half g_W3r_hi[1024 * 2048], g_W3r_lo[1024 * 2048];

// ---------------- PTX helpers (sm_80-legal only) -----------------------------
__device__ __forceinline__ uint32_t smem_u32(const void* p) {
    uint32_t a;
    asm("{ .reg .u64 t; cvta.to.shared.u64 t, %1; cvt.u32.u64 %0, t; }" : "=r"(a) : "l"(p));
    return a;
}
#define CP_ASYNC16(dst, src) \
    asm volatile("cp.async.cg.shared.global [%0], [%1], 16;" :: "r"(dst), "l"(src) : "memory")
#define CP_COMMIT() asm volatile("cp.async.commit_group;" ::: "memory")
#define CP_WAIT(n)  asm volatile("cp.async.wait_group %0;" :: "n"(n) : "memory")
#define LDSM4(r, a)                                                                   \
    asm volatile("ldmatrix.sync.aligned.m8n8.x4.shared.b16 {%0,%1,%2,%3}, [%4];"      \
        : "=r"((r)[0]), "=r"((r)[1]), "=r"((r)[2]), "=r"((r)[3]) : "r"(a))
__device__ __forceinline__ void mma16816(float* c, const uint32_t* a, const uint32_t* b) {
    asm volatile(
        "mma.sync.aligned.m16n8k16.row.col.f32.f16.f16.f32 "
        "{%0,%1,%2,%3}, {%4,%5,%6,%7}, {%8,%9}, {%0,%1,%2,%3};"
        : "+f"(c[0]), "+f"(c[1]), "+f"(c[2]), "+f"(c[3])
        : "r"(a[0]), "r"(a[1]), "r"(a[2]), "r"(a[3]), "r"(b[0]), "r"(b[1]));
}

// ---------------- edge / CSR utils -------------------------------------------
// detect edge dtype AND zero the degree counters (one small launch)
__global__ void detect_zero_kernel(const int* __restrict__ w, int npairs, int N) {
    __shared__ int f;
    if (threadIdx.x == 0) f = 0;
    __syncthreads();
    for (int i = threadIdx.x; i < npairs; i += blockDim.x)
        if (w[2 * i + 1] != 0) f = 1;
    for (int i = threadIdx.x; i < N; i += blockDim.x) g_cnt_i[i] = 0;
    __syncthreads();
    if (threadIdx.x == 0) g_is64 = f ? 0 : 1;
}
__device__ __forceinline__ int edge_at(const void* ei, long long i, int is64) {
    return is64 ? (int)((const long long*)ei)[i] : ((const int*)ei)[i];
}
__global__ void count_deg_kernel(const void* __restrict__ ei, int E) {
    int e = blockIdx.x * blockDim.x + threadIdx.x;
    if (e >= E) return;
    atomicAdd(&g_cnt_i[edge_at(ei, (long long)E + e, g_is64)], 1);
}
// single-block exclusive scan of g_cnt_i -> rowptr/cursor, plus invcnt
__global__ void scan_inv_kernel(int N) {
    __shared__ int smv[1024];
    __shared__ int carry;
    const int tid = threadIdx.x;
    if (tid == 0) carry = 0;
    __syncthreads();
    for (int base = 0; base < N; base += 1024) {
        int v = (base + tid < N) ? g_cnt_i[base + tid] : 0;
        smv[tid] = v;
        __syncthreads();
        for (int off = 1; off < 1024; off <<= 1) {
            int t = (tid >= off) ? smv[tid - off] : 0;
            __syncthreads();
            smv[tid] += t;
            __syncthreads();
        }
        const int excl = smv[tid] - v + carry;
        if (base + tid < N) {
            g_rowptr[base + tid] = excl;
            g_cursor[base + tid] = excl;
            g_invcnt[base + tid] = 1.0f / (float)max(v, 1);
        }
        const int tot = smv[1023];
        __syncthreads();
        if (tid == 0) carry += tot;
        __syncthreads();
    }
    if (tid == 0) g_rowptr[N] = carry;
}
__global__ void fill_csr_kernel(const void* __restrict__ ei, int E) {
    int e = blockIdx.x * blockDim.x + threadIdx.x;
    if (e >= E) return;
    const int is64 = g_is64;
    const int s = edge_at(ei, e, is64);
    const int d = edge_at(ei, (long long)E + e, is64);
    g_csr[atomicAdd(&g_cursor[d], 1)] = s;
}
// AGG[node,:] = sum_{src in neigh(node)} S[src,:]
__global__ void gather_sum_kernel(const float* __restrict__ S, float* __restrict__ AGG, int D) {
    const int node = blockIdx.x;
    const int col = blockIdx.y * 512 + threadIdx.x * 4;
    if (col >= D) return;
    const int beg = g_rowptr[node], end = g_rowptr[node + 1];
    float4 acc = make_float4(0.f, 0.f, 0.f, 0.f);
    for (int i = beg; i < end; i++) {
        const float4 v = *(const float4*)(S + (long long)g_csr[i] * D + col);
        acc.x += v.x; acc.y += v.y; acc.z += v.z; acc.w += v.w;
    }
    *(float4*)(AGG + (long long)node * D + col) = acc;
}

// ---------------- conversions ------------------------------------------------
__device__ __forceinline__ void splitw(float f, __half& h, __half& l) {
    h = __float2half_rn(f);
    l = __float2half_rn(f - __half2float(h));
}
// layer-1 prep: per node build Xh = [mean_x | x] (fp16); extra blocks split W1.
// node blocks: 4 nodes x 64 threads. W1 blocks: 32x32 transpose-split tiles.
__global__ void l1_prep_kernel(const float* __restrict__ x, int N, int nodeBlocks,
                               const float* __restrict__ W1l, const float* __restrict__ W1r,
                               int F, int D1) {
    __shared__ float t[32][33];
    const int bid = blockIdx.x;
    if (bid < nodeBlocks) {
        const int sub = threadIdx.x >> 6;          // 0..3
        const int st  = threadIdx.x & 63;          // 0..63
        const int node = bid * 4 + sub;
        if (node >= N) return;
        if (st < 32) {
            const int col = st * 4;
            const int beg = g_rowptr[node], end = g_rowptr[node + 1];
            float4 acc = make_float4(0.f, 0.f, 0.f, 0.f);
            for (int i = beg; i < end; i++) {
                const float4 v = *(const float4*)(x + (long long)g_csr[i] * 128 + col);
                acc.x += v.x; acc.y += v.y; acc.z += v.z; acc.w += v.w;
            }
            const float ic = g_invcnt[node];
            __half2* dst = (__half2*)(g_Xh + (long long)node * 256 + col);
            dst[0] = __floats2half2_rn(acc.x * ic, acc.y * ic);
            dst[1] = __floats2half2_rn(acc.z * ic, acc.w * ic);
        } else {
            const int col = (st - 32) * 4;
            const float4 v = *(const float4*)(x + (long long)node * 128 + col);
            __half2* dst = (__half2*)(g_Xh + (long long)node * 256 + 128 + col);
            dst[0] = __floats2half2_rn(v.x, v.y);
            dst[1] = __floats2half2_rn(v.z, v.w);
        }
    } else {
        // W1 split tiles: t in [0, 2*(D1/32)*(F/32))
        const int tI = bid - nodeBlocks;
        const int perMat = (D1 / 32) * (F / 32);
        const int mat = tI / perMat;               // 0 = W1l (kofs 0), 1 = W1r (kofs F)
        const int tile = tI % perMat;
        const int n0 = (tile % (D1 / 32)) * 32;
        const int k0 = (tile / (D1 / 32)) * 32;
        const float* W = mat ? W1r : W1l;
        const int kofs = mat ? F : 0;
        const int tx = threadIdx.x & 31, ty = threadIdx.x >> 5;   // 32 x 8
        for (int dy = ty; dy < 32; dy += 8)
            t[dy][tx] = W[(long long)(k0 + dy) * D1 + n0 + tx];
        __syncthreads();
        for (int dy = ty; dy < 32; dy += 8) {
            int n = n0 + dy, k = k0 + tx;
            __half h, l;
            splitw(t[tx][dy], h, l);
            g_W1_hi[(long long)n * 256 + kofs + k] = h;
            g_W1_lo[(long long)n * 256 + kofs + k] = l;
        }
    }
}
// W[K,N] f32 -> T[n][k] hi/lo fp16 (row stride = K)
__global__ void wsplitT_kernel(const float* __restrict__ W, __half* __restrict__ Th,
                               __half* __restrict__ Tl, int K, int N) {
    __shared__ float t[32][33];
    int n0 = blockIdx.x * 32, k0 = blockIdx.y * 32;
    for (int dy = threadIdx.y; dy < 32; dy += 8)
        t[dy][threadIdx.x] = W[(long long)(k0 + dy) * N + n0 + threadIdx.x];
    __syncthreads();
    for (int dy = threadIdx.y; dy < 32; dy += 8) {
        int n = n0 + dy, k = k0 + threadIdx.x;
        __half h, l;
        splitw(t[threadIdx.x][dy], h, l);
        Th[(long long)n * K + k] = h;
        Tl[(long long)n * K + k] = l;
    }
}

// ---------------- mma.sync GEMM (2-product fp16) ------------------------------
// D = act(A@Bh^T + A@Bl^T + addmat*rowscale + bias)
// A: [M,K] fp16; Bh/Bl: [Nc,K] fp16. Outputs C (f32) and/or Oh (fp16).
#define STG        4
#define STAGE_BY   49152              // A 16K | Bh 16K | Bl 16K
#define SMEM_TOT   (STG * STAGE_BY)   // 192 KB

__global__ __launch_bounds__(256, 1)
void mma_gemm(const __half* __restrict__ A,
              const __half* __restrict__ Bh, const __half* __restrict__ Bl,
              float* __restrict__ C, __half* __restrict__ Oh,
              const float* __restrict__ addmat, const float* __restrict__ rowscale,
              const float* __restrict__ bias, int M, int Nc, int K, int relu) {
    extern __shared__ char sm[];
    const uint32_t sb = smem_u32(sm);
    const int tid = threadIdx.x, wid = tid >> 5, lane = tid & 31;
    const int m0 = blockIdx.y * 128, n0 = blockIdx.x * 128;
    const int nk = K >> 6;

    const int lrow = tid >> 1;
    const int u0   = (tid & 1) * 4;
    const bool arow_ok = (m0 + lrow) < M;
    const __half* gA  = A  + (long long)(m0 + lrow) * K;
    const __half* gBh = Bh + (long long)(n0 + lrow) * K;
    const __half* gBl = Bl + (long long)(n0 + lrow) * K;
    uint32_t sst[4];
#pragma unroll
    for (int j = 0; j < 4; j++) {
        int u = u0 + j;
        sst[j] = lrow * 128 + ((u ^ (lrow & 7)) * 16);
    }

    float acc[4][4][4];
#pragma unroll
    for (int a = 0; a < 4; a++)
#pragma unroll
        for (int b = 0; b < 4; b++)
#pragma unroll
            for (int c = 0; c < 4; c++) acc[a][b][c] = 0.f;

    const int m0w = (wid & 1) * 64, n0w = (wid >> 1) * 32;

    auto issue = [&](int kt) {
        const uint32_t base = sb + (kt % STG) * STAGE_BY;
        const int k0 = kt * 64;
#pragma unroll
        for (int j = 0; j < 4; j++) {
            const int u = u0 + j;
            if (arow_ok) CP_ASYNC16(base + sst[j], gA + k0 + u * 8);
            CP_ASYNC16(base + 16384 + sst[j], gBh + k0 + u * 8);
            CP_ASYNC16(base + 32768 + sst[j], gBl + k0 + u * 8);
        }
        CP_COMMIT();
    };

    const int pro = nk < 3 ? nk : 3;
    for (int p = 0; p < pro; p++) issue(p);

    for (int kt = 0; kt < nk; kt++) {
        const int pend = nk - 1 - kt;                    // stages still needed after this
        if (pend >= 2)      CP_WAIT(2);
        else if (pend == 1) CP_WAIT(1);
        else                CP_WAIT(0);
        __syncthreads();                  // all warps done reading slot (kt-1)%4
        if (kt + 3 < nk) issue(kt + 3);   // refill that slot, overlapped w/ compute

        const uint32_t Ab = sb + (kt % STG) * STAGE_BY;
#pragma unroll
        for (int ks = 0; ks < 4; ks++) {
            uint32_t af[4][4];
#pragma unroll
            for (int mc = 0; mc < 4; mc++) {
                const int r = m0w + mc * 16 + (lane & 15);
                const int u = ks * 2 + (lane >> 4);
                LDSM4(af[mc], Ab + r * 128 + ((u ^ (r & 7)) * 16));
            }
            uint32_t bfh[2][4], bfl[2][4];
#pragma unroll
            for (int pr = 0; pr < 2; pr++) {
                const int n = n0w + pr * 16 + ((lane >> 4) & 1) * 8 + (lane & 7);
                const int u = ks * 2 + ((lane >> 3) & 1);
                const uint32_t bd = Ab + 16384 + n * 128 + ((u ^ (n & 7)) * 16);
                LDSM4(bfh[pr], bd);
                LDSM4(bfl[pr], bd + 16384);
            }
#pragma unroll
            for (int mc = 0; mc < 4; mc++)
#pragma unroll
                for (int pr = 0; pr < 2; pr++)
#pragma unroll
                    for (int h = 0; h < 2; h++) {
                        const int nc = pr * 2 + h;
                        mma16816(acc[mc][nc], af[mc], &bfh[pr][h * 2]);
                        mma16816(acc[mc][nc], af[mc], &bfl[pr][h * 2]);
                    }
        }
    }

    // ---- fused epilogue ----
#pragma unroll
    for (int mc = 0; mc < 4; mc++) {
        const int r0 = m0 + m0w + mc * 16 + (lane >> 2);
        const int r1 = r0 + 8;
        const float rs0 = (rowscale && r0 < M) ? rowscale[r0] : 0.f;
        const float rs1 = (rowscale && r1 < M) ? rowscale[r1] : 0.f;
#pragma unroll
        for (int nc = 0; nc < 4; nc++) {
            const int col = n0 + n0w + nc * 8 + (lane & 3) * 2;
            float2 bv = make_float2(0.f, 0.f);
            if (bias) bv = *(const float2*)(bias + col);
#pragma unroll
            for (int half_ = 0; half_ < 2; half_++) {
                const int r = half_ ? r1 : r0;
                if (r >= M) continue;
                const float rs = half_ ? rs1 : rs0;
                float2 v = make_float2(acc[mc][nc][2 * half_], acc[mc][nc][2 * half_ + 1]);
                if (addmat) {
                    float2 a = *(const float2*)(addmat + (long long)r * Nc + col);
                    v.x += a.x * rs; v.y += a.y * rs;
                }
                v.x += bv.x; v.y += bv.y;
                if (relu) { v.x = fmaxf(v.x, 0.f); v.y = fmaxf(v.y, 0.f); }
                if (C)  *(float2*)(C + (long long)r * Nc + col) = v;
                if (Oh) *(__half2*)(Oh + (long long)r * Nc + col) = __floats2half2_rn(v.x, v.y);
            }
        }
    }
}

// ---------------- L2 normalize (D3 = 1024) -----------------------------------
__global__ void l2norm_kernel(const float* __restrict__ H, float* __restrict__ out) {
    const int row = blockIdx.x;
    const float4* h = (const float4*)H + (long long)row * 256;
    float4 v = h[threadIdx.x];
    float s = v.x * v.x + v.y * v.y + v.z * v.z + v.w * v.w;
#pragma unroll
    for (int o = 16; o; o >>= 1) s += __shfl_xor_sync(0xFFFFFFFFu, s, o);
    __shared__ float ws[8];
    if ((threadIdx.x & 31) == 0) ws[threadIdx.x >> 5] = s;
    __syncthreads();
    if (threadIdx.x < 8) {
        float t = ws[threadIdx.x];
#pragma unroll
        for (int o = 4; o; o >>= 1) t += __shfl_xor_sync(0xFFu, t, o);
        if (threadIdx.x == 0) ws[0] = t;
    }
    __syncthreads();
    const float inv = 1.0f / fmaxf(sqrtf(ws[0]), 1e-12f);
    ((float4*)out)[(long long)row * 256 + threadIdx.x] =
        make_float4(v.x * inv, v.y * inv, v.z * inv, v.w * inv);
}

// ---------------- host -------------------------------------------------------
static void run_mma(const __half* A, const __half* Bh, const __half* Bl,
                    float* C, __half* Oh, const float* addmat, const float* rowscale,
                    const float* bias, int M, int Nc, int K, int relu) {
    static bool attr_set = false;
    if (!attr_set) {
        cudaFuncSetAttribute(mma_gemm, cudaFuncAttributeMaxDynamicSharedMemorySize, SMEM_TOT);
        attr_set = true;
    }
    dim3 grid(Nc / 128, (M + 127) / 128);
    mma_gemm<<<grid, 256, SMEM_TOT>>>(A, Bh, Bl, C, Oh, addmat, rowscale, bias, M, Nc, K, relu);
}

extern "C" void kernel_launch(void* const* d_in, const int* in_sizes, int n_in,
                              void* d_out, int out_size) {
    const float* x   = (const float*)d_in[0];
    const void*  ei  = d_in[2];
    const float* W1l = (const float*)d_in[3];
    const float* W1r = (const float*)d_in[4];
    const float* b1  = (const float*)d_in[5];
    const float* W2l = (const float*)d_in[6];
    const float* W2r = (const float*)d_in[7];
    const float* b2  = (const float*)d_in[8];
    const float* W3l = (const float*)d_in[9];
    const float* W3r = (const float*)d_in[10];
    const float* b3  = (const float*)d_in[11];

    const int D1 = in_sizes[5];       // 2048
    const int D2 = in_sizes[8];       // 2048
    const int D3 = in_sizes[11];      // 1024
    const int F  = in_sizes[3] / D1;  // 128
    const int N  = in_sizes[0] / F;   // 50000
    const int E  = in_sizes[2] / 2;   // 400000

    float *P, *AGG, *H, *invc;
    cudaGetSymbolAddress((void**)&P, g_P);
    cudaGetSymbolAddress((void**)&AGG, g_AGG);
    cudaGetSymbolAddress((void**)&H, g_H);
    cudaGetSymbolAddress((void**)&invc, g_invcnt);
    __half *Xh, *A1h, *W1h, *W1lo, *W2lh, *W2ll, *W2rh, *W2rl, *W3lh, *W3ll, *W3rh, *W3rl;
    cudaGetSymbolAddress((void**)&Xh, g_Xh);
    cudaGetSymbolAddress((void**)&A1h, g_A1h);
    cudaGetSymbolAddress((void**)&W1h, g_W1_hi);
    cudaGetSymbolAddress((void**)&W1lo, g_W1_lo);
    cudaGetSymbolAddress((void**)&W2lh, g_W2l_hi);
    cudaGetSymbolAddress((void**)&W2ll, g_W2l_lo);
    cudaGetSymbolAddress((void**)&W2rh, g_W2r_hi);
    cudaGetSymbolAddress((void**)&W2rl, g_W2r_lo);
    cudaGetSymbolAddress((void**)&W3lh, g_W3l_hi);
    cudaGetSymbolAddress((void**)&W3ll, g_W3l_lo);
    cudaGetSymbolAddress((void**)&W3rh, g_W3r_hi);
    cudaGetSymbolAddress((void**)&W3rl, g_W3r_lo);

    // A2 (fp16, N*D2 elems = 200 MB) aliases g_P (f32, 400 MB): P is dead after
    // the layer-2 gather has consumed it.
    __half* A2h = (__half*)P;

    float* out = (float*)d_out;
    const int TPB = 256;
    const int eb = (E + TPB - 1) / TPB;

    // ---- prologue (no memsets; GEMM1 lands early for ncu sampling) ----
    detect_zero_kernel<<<1, 256>>>((const int*)ei, E < 1024 ? E : 1024, N);
    count_deg_kernel<<<eb, TPB>>>(ei, E);
    scan_inv_kernel<<<1, 1024>>>(N);
    fill_csr_kernel<<<eb, TPB>>>(ei, E);

    // ---- layer 1 prep: Xh = [mean_x | x] fp16, + W1 transpose/split ----
    const int nodeBlocks = (N + 3) / 4;
    const int w1Tiles = 2 * (D1 / 32) * (F / 32);
    l1_prep_kernel<<<nodeBlocks + w1Tiles, 256>>>(x, N, nodeBlocks, W1l, W1r, F, D1);
    run_mma(Xh, W1h, W1lo, nullptr, A1h, nullptr, nullptr, b1, N, D1, 2 * F, 1);

    // ---- remaining weight splits ----
    dim3 tb(32, 8);
    wsplitT_kernel<<<dim3(D2 / 32, D1 / 32), tb>>>(W2l, W2lh, W2ll, D1, D2);
    wsplitT_kernel<<<dim3(D2 / 32, D1 / 32), tb>>>(W2r, W2rh, W2rl, D1, D2);
    wsplitT_kernel<<<dim3(D3 / 32, D2 / 32), tb>>>(W3l, W3lh, W3ll, D2, D3);
    wsplitT_kernel<<<dim3(D3 / 32, D2 / 32), tb>>>(W3r, W3rh, W3rl, D2, D3);

    // ---- layer 2: P = H1@W2l; AGG = gather(P); H2 -> A2h (in P's memory) ----
    run_mma(A1h, W2lh, W2ll, P, nullptr, nullptr, nullptr, nullptr, N, D2, D1, 0);
    gather_sum_kernel<<<dim3(N, (D2 + 511) / 512), 128>>>(P, AGG, D2);
    run_mma(A1h, W2rh, W2rl, nullptr, A2h, AGG, invc, b2, N, D2, D1, 1);

    // ---- layer 3: H = H2@W3l; AGG = gather(H); H3 -> H ----
    run_mma(A2h, W3lh, W3ll, H, nullptr, nullptr, nullptr, nullptr, N, D3, D2, 0);
    gather_sum_kernel<<<dim3(N, (D3 + 511) / 512), 128>>>(H, AGG, D3);
    run_mma(A2h, W3rh, W3rl, H, nullptr, AGG, invc, b3, N, D3, D2, 1);

    // ---- normalize ----
    l2norm_kernel<<<N, 256>>>(H, out);
    (void)n_in; (void)out_size;
}

// round 8
// speedup vs baseline: 6.5413x; 1.9158x over previous
#include <cuda_runtime.h>
#include <cuda_fp16.h>
#include <cstdint>

// ===========================================================================
// GraphSAGE 3-layer forward, plain sm_100 target.
// R8 = R7 resubmit (infra failure last round; kernel never ran).
// Single-product fp16 GEMM (A fp16, W fp16, fp32 acc) -> 1.31 TFLOP HMMA.
// 3-stage cp.async pipeline, 2 CTAs/SM, CSR gather, fused epilogues.
// ===========================================================================

#define NMAX 50000
#define DMAX 2048
#define EMAX 450000

static __device__ float g_P  [(long long)NMAX * DMAX];   // f32 scratch; later aliased as A2 (fp16)
static __device__ float g_AGG[(long long)NMAX * DMAX];
static __device__ float g_H  [(long long)NMAX * DMAX];
static __device__ int   g_cnt_i [NMAX];
static __device__ float g_invcnt[NMAX];
static __device__ int   g_rowptr[NMAX + 1];
static __device__ int   g_cursor[NMAX];
static __device__ int   g_csr   [EMAX];
static __device__ int   g_is64;

static __device__ __half g_Xh [(long long)NMAX * 256];
static __device__ __half g_A1h[(long long)NMAX * DMAX];
static __device__ __half g_W1 [2048 * 256];
static __device__ __half g_W2l[2048 * 2048];
static __device__ __half g_W2r[2048 * 2048];
static __device__ __half g_W3l[1024 * 2048];
static __device__ __half g_W3r[1024 * 2048];

// ---------------- PTX helpers (sm_80-legal only) -----------------------------
__device__ __forceinline__ uint32_t smem_u32(const void* p) {
    uint32_t a;
    asm("{ .reg .u64 t; cvta.to.shared.u64 t, %1; cvt.u32.u64 %0, t; }" : "=r"(a) : "l"(p));
    return a;
}
#define CP_ASYNC16(dst, src) \
    asm volatile("cp.async.cg.shared.global [%0], [%1], 16;" :: "r"(dst), "l"(src) : "memory")
#define CP_COMMIT() asm volatile("cp.async.commit_group;" ::: "memory")
#define CP_WAIT(n)  asm volatile("cp.async.wait_group %0;" :: "n"(n) : "memory")
#define LDSM4(r, a)                                                                   \
    asm volatile("ldmatrix.sync.aligned.m8n8.x4.shared.b16 {%0,%1,%2,%3}, [%4];"      \
        : "=r"((r)[0]), "=r"((r)[1]), "=r"((r)[2]), "=r"((r)[3]) : "r"(a))
__device__ __forceinline__ void mma16816(float* c, const uint32_t* a, const uint32_t* b) {
    asm volatile(
        "mma.sync.aligned.m16n8k16.row.col.f32.f16.f16.f32 "
        "{%0,%1,%2,%3}, {%4,%5,%6,%7}, {%8,%9}, {%0,%1,%2,%3};"
        : "+f"(c[0]), "+f"(c[1]), "+f"(c[2]), "+f"(c[3])
        : "r"(a[0]), "r"(a[1]), "r"(a[2]), "r"(a[3]), "r"(b[0]), "r"(b[1]));
}

// ---------------- edge / CSR utils -------------------------------------------
__global__ void detect_zero_kernel(const int* __restrict__ w, int npairs, int N) {
    __shared__ int f;
    if (threadIdx.x == 0) f = 0;
    __syncthreads();
    for (int i = threadIdx.x; i < npairs; i += blockDim.x)
        if (w[2 * i + 1] != 0) f = 1;
    for (int i = threadIdx.x; i < N; i += blockDim.x) g_cnt_i[i] = 0;
    __syncthreads();
    if (threadIdx.x == 0) g_is64 = f ? 0 : 1;
}
__device__ __forceinline__ int edge_at(const void* ei, long long i, int is64) {
    return is64 ? (int)((const long long*)ei)[i] : ((const int*)ei)[i];
}
__global__ void count_deg_kernel(const void* __restrict__ ei, int E) {
    int e = blockIdx.x * blockDim.x + threadIdx.x;
    if (e >= E) return;
    atomicAdd(&g_cnt_i[edge_at(ei, (long long)E + e, g_is64)], 1);
}
__global__ void scan_inv_kernel(int N) {
    __shared__ int smv[1024];
    __shared__ int carry;
    const int tid = threadIdx.x;
    if (tid == 0) carry = 0;
    __syncthreads();
    for (int base = 0; base < N; base += 1024) {
        int v = (base + tid < N) ? g_cnt_i[base + tid] : 0;
        smv[tid] = v;
        __syncthreads();
        for (int off = 1; off < 1024; off <<= 1) {
            int t = (tid >= off) ? smv[tid - off] : 0;
            __syncthreads();
            smv[tid] += t;
            __syncthreads();
        }
        const int excl = smv[tid] - v + carry;
        if (base + tid < N) {
            g_rowptr[base + tid] = excl;
            g_cursor[base + tid] = excl;
            g_invcnt[base + tid] = 1.0f / (float)max(v, 1);
        }
        const int tot = smv[1023];
        __syncthreads();
        if (tid == 0) carry += tot;
        __syncthreads();
    }
    if (tid == 0) g_rowptr[N] = carry;
}
__global__ void fill_csr_kernel(const void* __restrict__ ei, int E) {
    int e = blockIdx.x * blockDim.x + threadIdx.x;
    if (e >= E) return;
    const int is64 = g_is64;
    const int s = edge_at(ei, e, is64);
    const int d = edge_at(ei, (long long)E + e, is64);
    g_csr[atomicAdd(&g_cursor[d], 1)] = s;
}
__global__ void gather_sum_kernel(const float* __restrict__ S, float* __restrict__ AGG, int D) {
    const int node = blockIdx.x;
    const int col = blockIdx.y * 512 + threadIdx.x * 4;
    if (col >= D) return;
    const int beg = g_rowptr[node], end = g_rowptr[node + 1];
    float4 acc = make_float4(0.f, 0.f, 0.f, 0.f);
    for (int i = beg; i < end; i++) {
        const float4 v = *(const float4*)(S + (long long)g_csr[i] * D + col);
        acc.x += v.x; acc.y += v.y; acc.z += v.z; acc.w += v.w;
    }
    *(float4*)(AGG + (long long)node * D + col) = acc;
}

// ---------------- layer-1 prep + weight conversion ---------------------------
// per node build Xh = [mean_x | x] fp16; extra blocks transpose+convert W1.
__global__ void l1_prep_kernel(const float* __restrict__ x, int N, int nodeBlocks,
                               const float* __restrict__ W1l, const float* __restrict__ W1r,
                               int F, int D1) {
    __shared__ float t[32][33];
    const int bid = blockIdx.x;
    if (bid < nodeBlocks) {
        const int sub = threadIdx.x >> 6;          // 0..3
        const int st  = threadIdx.x & 63;          // 0..63
        const int node = bid * 4 + sub;
        if (node >= N) return;
        if (st < 32) {
            const int col = st * 4;
            const int beg = g_rowptr[node], end = g_rowptr[node + 1];
            float4 acc = make_float4(0.f, 0.f, 0.f, 0.f);
            for (int i = beg; i < end; i++) {
                const float4 v = *(const float4*)(x + (long long)g_csr[i] * 128 + col);
                acc.x += v.x; acc.y += v.y; acc.z += v.z; acc.w += v.w;
            }
            const float ic = g_invcnt[node];
            __half2* dst = (__half2*)(g_Xh + (long long)node * 256 + col);
            dst[0] = __floats2half2_rn(acc.x * ic, acc.y * ic);
            dst[1] = __floats2half2_rn(acc.z * ic, acc.w * ic);
        } else {
            const int col = (st - 32) * 4;
            const float4 v = *(const float4*)(x + (long long)node * 128 + col);
            __half2* dst = (__half2*)(g_Xh + (long long)node * 256 + 128 + col);
            dst[0] = __floats2half2_rn(v.x, v.y);
            dst[1] = __floats2half2_rn(v.z, v.w);
        }
    } else {
        const int tI = bid - nodeBlocks;
        const int perMat = (D1 / 32) * (F / 32);
        const int mat = tI / perMat;               // 0 = W1l (kofs 0), 1 = W1r (kofs F)
        const int tile = tI % perMat;
        const int n0 = (tile % (D1 / 32)) * 32;
        const int k0 = (tile / (D1 / 32)) * 32;
        const float* W = mat ? W1r : W1l;
        const int kofs = mat ? F : 0;
        const int tx = threadIdx.x & 31, ty = threadIdx.x >> 5;   // 32 x 8
        for (int dy = ty; dy < 32; dy += 8)
            t[dy][tx] = W[(long long)(k0 + dy) * D1 + n0 + tx];
        __syncthreads();
        for (int dy = ty; dy < 32; dy += 8) {
            int n = n0 + dy, k = k0 + tx;
            g_W1[(long long)n * 256 + kofs + k] = __float2half_rn(t[tx][dy]);
        }
    }
}
// W[K,N] f32 -> T[n][k] fp16 (row stride = K)
__global__ void wconvT_kernel(const float* __restrict__ W, __half* __restrict__ T,
                              int K, int N) {
    __shared__ float t[32][33];
    int n0 = blockIdx.x * 32, k0 = blockIdx.y * 32;
    for (int dy = threadIdx.y; dy < 32; dy += 8)
        t[dy][threadIdx.x] = W[(long long)(k0 + dy) * N + n0 + threadIdx.x];
    __syncthreads();
    for (int dy = threadIdx.y; dy < 32; dy += 8) {
        int n = n0 + dy, k = k0 + threadIdx.x;
        T[(long long)n * K + k] = __float2half_rn(t[threadIdx.x][dy]);
    }
}

// ---------------- mma.sync GEMM (single-product fp16) -------------------------
// D = act(A@B^T + addmat*rowscale + bias);  A [M,K] fp16, B [Nc,K] fp16.
#define STG        3
#define STAGE_BY   32768              // A 16K | B 16K
#define SMEM_TOT   (STG * STAGE_BY)   // 96 KB -> 2 CTAs/SM

__global__ __launch_bounds__(256, 2)
void mma_gemm(const __half* __restrict__ A, const __half* __restrict__ B,
              float* __restrict__ C, __half* __restrict__ Oh,
              const float* __restrict__ addmat, const float* __restrict__ rowscale,
              const float* __restrict__ bias, int M, int Nc, int K, int relu) {
    extern __shared__ char sm[];
    const uint32_t sb = smem_u32(sm);
    const int tid = threadIdx.x, wid = tid >> 5, lane = tid & 31;
    const int m0 = blockIdx.y * 128, n0 = blockIdx.x * 128;
    const int nk = K >> 6;

    const int lrow = tid >> 1;
    const int u0   = (tid & 1) * 4;
    const bool arow_ok = (m0 + lrow) < M;
    const __half* gA = A + (long long)(m0 + lrow) * K;
    const __half* gB = B + (long long)(n0 + lrow) * K;
    uint32_t sst[4];
#pragma unroll
    for (int j = 0; j < 4; j++) {
        int u = u0 + j;
        sst[j] = lrow * 128 + ((u ^ (lrow & 7)) * 16);
    }

    float acc[4][4][4];
#pragma unroll
    for (int a = 0; a < 4; a++)
#pragma unroll
        for (int b = 0; b < 4; b++)
#pragma unroll
            for (int c = 0; c < 4; c++) acc[a][b][c] = 0.f;

    const int m0w = (wid & 1) * 64, n0w = (wid >> 1) * 32;

    auto issue = [&](int kt) {
        const uint32_t base = sb + (kt % STG) * STAGE_BY;
        const int k0 = kt * 64;
#pragma unroll
        for (int j = 0; j < 4; j++) {
            const int u = u0 + j;
            if (arow_ok) CP_ASYNC16(base + sst[j], gA + k0 + u * 8);
            CP_ASYNC16(base + 16384 + sst[j], gB + k0 + u * 8);
        }
        CP_COMMIT();
    };

    const int pro = nk < 2 ? nk : 2;
    for (int p = 0; p < pro; p++) issue(p);

    for (int kt = 0; kt < nk; kt++) {
        if (kt + 1 < nk) CP_WAIT(1);
        else             CP_WAIT(0);
        __syncthreads();                 // all warps done reading slot (kt-1)%3
        if (kt + 2 < nk) issue(kt + 2);  // refill that slot, overlapped w/ compute

        const uint32_t Ab = sb + (kt % STG) * STAGE_BY;
#pragma unroll
        for (int ks = 0; ks < 4; ks++) {
            uint32_t af[4][4];
#pragma unroll
            for (int mc = 0; mc < 4; mc++) {
                const int r = m0w + mc * 16 + (lane & 15);
                const int u = ks * 2 + (lane >> 4);
                LDSM4(af[mc], Ab + r * 128 + ((u ^ (r & 7)) * 16));
            }
            uint32_t bf[2][4];
#pragma unroll
            for (int pr = 0; pr < 2; pr++) {
                const int n = n0w + pr * 16 + ((lane >> 4) & 1) * 8 + (lane & 7);
                const int u = ks * 2 + ((lane >> 3) & 1);
                LDSM4(bf[pr], Ab + 16384 + n * 128 + ((u ^ (n & 7)) * 16));
            }
#pragma unroll
            for (int mc = 0; mc < 4; mc++)
#pragma unroll
                for (int pr = 0; pr < 2; pr++)
#pragma unroll
                    for (int h = 0; h < 2; h++)
                        mma16816(acc[mc][pr * 2 + h], af[mc], &bf[pr][h * 2]);
        }
    }

    // ---- fused epilogue ----
#pragma unroll
    for (int mc = 0; mc < 4; mc++) {
        const int r0 = m0 + m0w + mc * 16 + (lane >> 2);
        const int r1 = r0 + 8;
        const float rs0 = (rowscale && r0 < M) ? rowscale[r0] : 0.f;
        const float rs1 = (rowscale && r1 < M) ? rowscale[r1] : 0.f;
#pragma unroll
        for (int nc = 0; nc < 4; nc++) {
            const int col = n0 + n0w + nc * 8 + (lane & 3) * 2;
            float2 bv = make_float2(0.f, 0.f);
            if (bias) bv = *(const float2*)(bias + col);
#pragma unroll
            for (int half_ = 0; half_ < 2; half_++) {
                const int r = half_ ? r1 : r0;
                if (r >= M) continue;
                const float rs = half_ ? rs1 : rs0;
                float2 v = make_float2(acc[mc][nc][2 * half_], acc[mc][nc][2 * half_ + 1]);
                if (addmat) {
                    float2 a = *(const float2*)(addmat + (long long)r * Nc + col);
                    v.x += a.x * rs; v.y += a.y * rs;
                }
                v.x += bv.x; v.y += bv.y;
                if (relu) { v.x = fmaxf(v.x, 0.f); v.y = fmaxf(v.y, 0.f); }
                if (C)  *(float2*)(C + (long long)r * Nc + col) = v;
                if (Oh) *(__half2*)(Oh + (long long)r * Nc + col) = __floats2half2_rn(v.x, v.y);
            }
        }
    }
}

// ---------------- L2 normalize (D3 = 1024) -----------------------------------
__global__ void l2norm_kernel(const float* __restrict__ H, float* __restrict__ out) {
    const int row = blockIdx.x;
    const float4* h = (const float4*)H + (long long)row * 256;
    float4 v = h[threadIdx.x];
    float s = v.x * v.x + v.y * v.y + v.z * v.z + v.w * v.w;
#pragma unroll
    for (int o = 16; o; o >>= 1) s += __shfl_xor_sync(0xFFFFFFFFu, s, o);
    __shared__ float ws[8];
    if ((threadIdx.x & 31) == 0) ws[threadIdx.x >> 5] = s;
    __syncthreads();
    if (threadIdx.x < 8) {
        float t = ws[threadIdx.x];
#pragma unroll
        for (int o = 4; o; o >>= 1) t += __shfl_xor_sync(0xFFu, t, o);
        if (threadIdx.x == 0) ws[0] = t;
    }
    __syncthreads();
    const float inv = 1.0f / fmaxf(sqrtf(ws[0]), 1e-12f);
    ((float4*)out)[(long long)row * 256 + threadIdx.x] =
        make_float4(v.x * inv, v.y * inv, v.z * inv, v.w * inv);
}

// ---------------- host -------------------------------------------------------
static void run_mma(const __half* A, const __half* B, float* C, __half* Oh,
                    const float* addmat, const float* rowscale,
                    const float* bias, int M, int Nc, int K, int relu) {
    static bool attr_set = false;
    if (!attr_set) {
        cudaFuncSetAttribute(mma_gemm, cudaFuncAttributeMaxDynamicSharedMemorySize, SMEM_TOT);
        attr_set = true;
    }
    dim3 grid(Nc / 128, (M + 127) / 128);
    mma_gemm<<<grid, 256, SMEM_TOT>>>(A, B, C, Oh, addmat, rowscale, bias, M, Nc, K, relu);
}

extern "C" void kernel_launch(void* const* d_in, const int* in_sizes, int n_in,
                              void* d_out, int out_size) {
    const float* x   = (const float*)d_in[0];
    const void*  ei  = d_in[2];
    const float* W1l = (const float*)d_in[3];
    const float* W1r = (const float*)d_in[4];
    const float* b1  = (const float*)d_in[5];
    const float* W2l = (const float*)d_in[6];
    const float* W2r = (const float*)d_in[7];
    const float* b2  = (const float*)d_in[8];
    const float* W3l = (const float*)d_in[9];
    const float* W3r = (const float*)d_in[10];
    const float* b3  = (const float*)d_in[11];

    const int D1 = in_sizes[5];       // 2048
    const int D2 = in_sizes[8];       // 2048
    const int D3 = in_sizes[11];      // 1024
    const int F  = in_sizes[3] / D1;  // 128
    const int N  = in_sizes[0] / F;   // 50000
    const int E  = in_sizes[2] / 2;   // 400000

    float *P, *AGG, *H, *invc;
    cudaGetSymbolAddress((void**)&P, g_P);
    cudaGetSymbolAddress((void**)&AGG, g_AGG);
    cudaGetSymbolAddress((void**)&H, g_H);
    cudaGetSymbolAddress((void**)&invc, g_invcnt);
    __half *Xh, *A1h, *W1, *W2lp, *W2rp, *W3lp, *W3rp;
    cudaGetSymbolAddress((void**)&Xh, g_Xh);
    cudaGetSymbolAddress((void**)&A1h, g_A1h);
    cudaGetSymbolAddress((void**)&W1, g_W1);
    cudaGetSymbolAddress((void**)&W2lp, g_W2l);
    cudaGetSymbolAddress((void**)&W2rp, g_W2r);
    cudaGetSymbolAddress((void**)&W3lp, g_W3l);
    cudaGetSymbolAddress((void**)&W3rp, g_W3r);

    // A2 (fp16, N*D2 = 200 MB) aliases g_P (f32, 400 MB): P is dead after the
    // layer-2 gather has consumed it.
    __half* A2h = (__half*)P;

    float* out = (float*)d_out;
    const int TPB = 256;
    const int eb = (E + TPB - 1) / TPB;

    // ---- prologue ----
    detect_zero_kernel<<<1, 256>>>((const int*)ei, E < 1024 ? E : 1024, N);
    count_deg_kernel<<<eb, TPB>>>(ei, E);
    scan_inv_kernel<<<1, 1024>>>(N);
    fill_csr_kernel<<<eb, TPB>>>(ei, E);

    // ---- layer 1 prep: Xh = [mean_x | x] fp16, + W1 transpose/convert ----
    const int nodeBlocks = (N + 3) / 4;
    const int w1Tiles = 2 * (D1 / 32) * (F / 32);
    l1_prep_kernel<<<nodeBlocks + w1Tiles, 256>>>(x, N, nodeBlocks, W1l, W1r, F, D1);
    run_mma(Xh, W1, nullptr, A1h, nullptr, nullptr, b1, N, D1, 2 * F, 1);

    // ---- remaining weight conversions ----
    dim3 tb(32, 8);
    wconvT_kernel<<<dim3(D2 / 32, D1 / 32), tb>>>(W2l, W2lp, D1, D2);
    wconvT_kernel<<<dim3(D2 / 32, D1 / 32), tb>>>(W2r, W2rp, D1, D2);
    wconvT_kernel<<<dim3(D3 / 32, D2 / 32), tb>>>(W3l, W3lp, D2, D3);
    wconvT_kernel<<<dim3(D3 / 32, D2 / 32), tb>>>(W3r, W3rp, D2, D3);

    // ---- layer 2: P = H1@W2l; AGG = gather(P); H2 -> A2h (in P's memory) ----
    run_mma(A1h, W2lp, P, nullptr, nullptr, nullptr, nullptr, N, D2, D1, 0);
    gather_sum_kernel<<<dim3(N, (D2 + 511) / 512), 128>>>(P, AGG, D2);
    run_mma(A1h, W2rp, nullptr, A2h, AGG, invc, b2, N, D2, D1, 1);

    // ---- layer 3: H = H2@W3l; AGG = gather(H); H3 -> H ----
    run_mma(A2h, W3lp, H, nullptr, nullptr, nullptr, nullptr, N, D3, D2, 0);
    gather_sum_kernel<<<dim3(N, (D3 + 511) / 512), 128>>>(H, AGG, D3);
    run_mma(A2h, W3rp, H, nullptr, AGG, invc, b3, N, D3, D2, 1);

    // ---- normalize ----
    l2norm_kernel<<<N, 256>>>(H, out);
    (void)n_in; (void)out_size;
}

// round 9
// speedup vs baseline: 6.6439x; 1.0157x over previous
#include <cuda_runtime.h>
#include <cuda_fp16.h>
#include <cstdint>

// ===========================================================================
// GraphSAGE 3-layer forward, plain sm_100 target.
// R9 = R8 + fp16 intermediate P: GEMM-a writes fp16, gathers read fp16 and
// accumulate fp32 -> halves the dominant gather traffic (~0.4 ms).
// Single-product fp16 GEMM, 3-stage cp.async, 2 CTAs/SM, CSR gather.
// ===========================================================================

#define NMAX 50000
#define DMAX 2048
#define EMAX 450000

static __device__ float g_P  [(long long)NMAX * DMAX];   // arena: P16 (fp16) + A2h (fp16)
static __device__ float g_AGG[(long long)NMAX * DMAX];
static __device__ float g_H  [(long long)NMAX * DMAX];
static __device__ int   g_cnt_i [NMAX];
static __device__ float g_invcnt[NMAX];
static __device__ int   g_rowptr[NMAX + 1];
static __device__ int   g_cursor[NMAX];
static __device__ int   g_csr   [EMAX];
static __device__ int   g_is64;

static __device__ __half g_Xh [(long long)NMAX * 256];
static __device__ __half g_A1h[(long long)NMAX * DMAX];
static __device__ __half g_W1 [2048 * 256];
static __device__ __half g_W2l[2048 * 2048];
static __device__ __half g_W2r[2048 * 2048];
static __device__ __half g_W3l[1024 * 2048];
static __device__ __half g_W3r[1024 * 2048];

// ---------------- PTX helpers (sm_80-legal only) -----------------------------
__device__ __forceinline__ uint32_t smem_u32(const void* p) {
    uint32_t a;
    asm("{ .reg .u64 t; cvta.to.shared.u64 t, %1; cvt.u32.u64 %0, t; }" : "=r"(a) : "l"(p));
    return a;
}
#define CP_ASYNC16(dst, src) \
    asm volatile("cp.async.cg.shared.global [%0], [%1], 16;" :: "r"(dst), "l"(src) : "memory")
#define CP_COMMIT() asm volatile("cp.async.commit_group;" ::: "memory")
#define CP_WAIT(n)  asm volatile("cp.async.wait_group %0;" :: "n"(n) : "memory")
#define LDSM4(r, a)                                                                   \
    asm volatile("ldmatrix.sync.aligned.m8n8.x4.shared.b16 {%0,%1,%2,%3}, [%4];"      \
        : "=r"((r)[0]), "=r"((r)[1]), "=r"((r)[2]), "=r"((r)[3]) : "r"(a))
__device__ __forceinline__ void mma16816(float* c, const uint32_t* a, const uint32_t* b) {
    asm volatile(
        "mma.sync.aligned.m16n8k16.row.col.f32.f16.f16.f32 "
        "{%0,%1,%2,%3}, {%4,%5,%6,%7}, {%8,%9}, {%0,%1,%2,%3};"
        : "+f"(c[0]), "+f"(c[1]), "+f"(c[2]), "+f"(c[3])
        : "r"(a[0]), "r"(a[1]), "r"(a[2]), "r"(a[3]), "r"(b[0]), "r"(b[1]));
}

// ---------------- edge / CSR utils -------------------------------------------
__global__ void detect_zero_kernel(const int* __restrict__ w, int npairs, int N) {
    __shared__ int f;
    if (threadIdx.x == 0) f = 0;
    __syncthreads();
    for (int i = threadIdx.x; i < npairs; i += blockDim.x)
        if (w[2 * i + 1] != 0) f = 1;
    for (int i = threadIdx.x; i < N; i += blockDim.x) g_cnt_i[i] = 0;
    __syncthreads();
    if (threadIdx.x == 0) g_is64 = f ? 0 : 1;
}
__device__ __forceinline__ int edge_at(const void* ei, long long i, int is64) {
    return is64 ? (int)((const long long*)ei)[i] : ((const int*)ei)[i];
}
__global__ void count_deg_kernel(const void* __restrict__ ei, int E) {
    int e = blockIdx.x * blockDim.x + threadIdx.x;
    if (e >= E) return;
    atomicAdd(&g_cnt_i[edge_at(ei, (long long)E + e, g_is64)], 1);
}
__global__ void scan_inv_kernel(int N) {
    __shared__ int smv[1024];
    __shared__ int carry;
    const int tid = threadIdx.x;
    if (tid == 0) carry = 0;
    __syncthreads();
    for (int base = 0; base < N; base += 1024) {
        int v = (base + tid < N) ? g_cnt_i[base + tid] : 0;
        smv[tid] = v;
        __syncthreads();
        for (int off = 1; off < 1024; off <<= 1) {
            int t = (tid >= off) ? smv[tid - off] : 0;
            __syncthreads();
            smv[tid] += t;
            __syncthreads();
        }
        const int excl = smv[tid] - v + carry;
        if (base + tid < N) {
            g_rowptr[base + tid] = excl;
            g_cursor[base + tid] = excl;
            g_invcnt[base + tid] = 1.0f / (float)max(v, 1);
        }
        const int tot = smv[1023];
        __syncthreads();
        if (tid == 0) carry += tot;
        __syncthreads();
    }
    if (tid == 0) g_rowptr[N] = carry;
}
__global__ void fill_csr_kernel(const void* __restrict__ ei, int E) {
    int e = blockIdx.x * blockDim.x + threadIdx.x;
    if (e >= E) return;
    const int is64 = g_is64;
    const int s = edge_at(ei, e, is64);
    const int d = edge_at(ei, (long long)E + e, is64);
    g_csr[atomicAdd(&g_cursor[d], 1)] = s;
}
// AGG[node,:] = sum_{src} S16[src,:]  (fp16 in, fp32 accumulate/out)
// thread handles 8 halves (16B); grid (N, D/1024), 128 threads
__global__ void gather_sum_h_kernel(const __half* __restrict__ S, float* __restrict__ AGG, int D) {
    const int node = blockIdx.x;
    const int col = (blockIdx.y * 128 + threadIdx.x) * 8;
    if (col >= D) return;
    const int beg = g_rowptr[node], end = g_rowptr[node + 1];
    float acc[8];
#pragma unroll
    for (int j = 0; j < 8; j++) acc[j] = 0.f;
    for (int i = beg; i < end; i++) {
        const uint4 v = *(const uint4*)(S + (long long)g_csr[i] * D + col);
        const __half2* h = (const __half2*)&v;
#pragma unroll
        for (int j = 0; j < 4; j++) {
            float2 f = __half22float2(h[j]);
            acc[2 * j] += f.x;
            acc[2 * j + 1] += f.y;
        }
    }
    float4* dst = (float4*)(AGG + (long long)node * D + col);
    dst[0] = make_float4(acc[0], acc[1], acc[2], acc[3]);
    dst[1] = make_float4(acc[4], acc[5], acc[6], acc[7]);
}

// ---------------- layer-1 prep + weight conversion ---------------------------
__global__ void l1_prep_kernel(const float* __restrict__ x, int N, int nodeBlocks,
                               const float* __restrict__ W1l, const float* __restrict__ W1r,
                               int F, int D1) {
    __shared__ float t[32][33];
    const int bid = blockIdx.x;
    if (bid < nodeBlocks) {
        const int sub = threadIdx.x >> 6;          // 0..3
        const int st  = threadIdx.x & 63;          // 0..63
        const int node = bid * 4 + sub;
        if (node >= N) return;
        if (st < 32) {
            const int col = st * 4;
            const int beg = g_rowptr[node], end = g_rowptr[node + 1];
            float4 acc = make_float4(0.f, 0.f, 0.f, 0.f);
            for (int i = beg; i < end; i++) {
                const float4 v = *(const float4*)(x + (long long)g_csr[i] * 128 + col);
                acc.x += v.x; acc.y += v.y; acc.z += v.z; acc.w += v.w;
            }
            const float ic = g_invcnt[node];
            __half2* dst = (__half2*)(g_Xh + (long long)node * 256 + col);
            dst[0] = __floats2half2_rn(acc.x * ic, acc.y * ic);
            dst[1] = __floats2half2_rn(acc.z * ic, acc.w * ic);
        } else {
            const int col = (st - 32) * 4;
            const float4 v = *(const float4*)(x + (long long)node * 128 + col);
            __half2* dst = (__half2*)(g_Xh + (long long)node * 256 + 128 + col);
            dst[0] = __floats2half2_rn(v.x, v.y);
            dst[1] = __floats2half2_rn(v.z, v.w);
        }
    } else {
        const int tI = bid - nodeBlocks;
        const int perMat = (D1 / 32) * (F / 32);
        const int mat = tI / perMat;               // 0 = W1l (kofs 0), 1 = W1r (kofs F)
        const int tile = tI % perMat;
        const int n0 = (tile % (D1 / 32)) * 32;
        const int k0 = (tile / (D1 / 32)) * 32;
        const float* W = mat ? W1r : W1l;
        const int kofs = mat ? F : 0;
        const int tx = threadIdx.x & 31, ty = threadIdx.x >> 5;   // 32 x 8
        for (int dy = ty; dy < 32; dy += 8)
            t[dy][tx] = W[(long long)(k0 + dy) * D1 + n0 + tx];
        __syncthreads();
        for (int dy = ty; dy < 32; dy += 8) {
            int n = n0 + dy, k = k0 + tx;
            g_W1[(long long)n * 256 + kofs + k] = __float2half_rn(t[tx][dy]);
        }
    }
}
__global__ void wconvT_kernel(const float* __restrict__ W, __half* __restrict__ T,
                              int K, int N) {
    __shared__ float t[32][33];
    int n0 = blockIdx.x * 32, k0 = blockIdx.y * 32;
    for (int dy = threadIdx.y; dy < 32; dy += 8)
        t[dy][threadIdx.x] = W[(long long)(k0 + dy) * N + n0 + threadIdx.x];
    __syncthreads();
    for (int dy = threadIdx.y; dy < 32; dy += 8) {
        int n = n0 + dy, k = k0 + threadIdx.x;
        T[(long long)n * K + k] = __float2half_rn(t[threadIdx.x][dy]);
    }
}

// ---------------- mma.sync GEMM (single-product fp16) -------------------------
#define STG        3
#define STAGE_BY   32768              // A 16K | B 16K
#define SMEM_TOT   (STG * STAGE_BY)   // 96 KB -> 2 CTAs/SM

__global__ __launch_bounds__(256, 2)
void mma_gemm(const __half* __restrict__ A, const __half* __restrict__ B,
              float* __restrict__ C, __half* __restrict__ Oh,
              const float* __restrict__ addmat, const float* __restrict__ rowscale,
              const float* __restrict__ bias, int M, int Nc, int K, int relu) {
    extern __shared__ char sm[];
    const uint32_t sb = smem_u32(sm);
    const int tid = threadIdx.x, wid = tid >> 5, lane = tid & 31;
    const int m0 = blockIdx.y * 128, n0 = blockIdx.x * 128;
    const int nk = K >> 6;

    const int lrow = tid >> 1;
    const int u0   = (tid & 1) * 4;
    const bool arow_ok = (m0 + lrow) < M;
    const __half* gA = A + (long long)(m0 + lrow) * K;
    const __half* gB = B + (long long)(n0 + lrow) * K;
    uint32_t sst[4];
#pragma unroll
    for (int j = 0; j < 4; j++) {
        int u = u0 + j;
        sst[j] = lrow * 128 + ((u ^ (lrow & 7)) * 16);
    }

    float acc[4][4][4];
#pragma unroll
    for (int a = 0; a < 4; a++)
#pragma unroll
        for (int b = 0; b < 4; b++)
#pragma unroll
            for (int c = 0; c < 4; c++) acc[a][b][c] = 0.f;

    const int m0w = (wid & 1) * 64, n0w = (wid >> 1) * 32;

    auto issue = [&](int kt) {
        const uint32_t base = sb + (kt % STG) * STAGE_BY;
        const int k0 = kt * 64;
#pragma unroll
        for (int j = 0; j < 4; j++) {
            const int u = u0 + j;
            if (arow_ok) CP_ASYNC16(base + sst[j], gA + k0 + u * 8);
            CP_ASYNC16(base + 16384 + sst[j], gB + k0 + u * 8);
        }
        CP_COMMIT();
    };

    const int pro = nk < 2 ? nk : 2;
    for (int p = 0; p < pro; p++) issue(p);

    for (int kt = 0; kt < nk; kt++) {
        if (kt + 1 < nk) CP_WAIT(1);
        else             CP_WAIT(0);
        __syncthreads();                 // all warps done reading slot (kt-1)%3
        if (kt + 2 < nk) issue(kt + 2);  // refill that slot, overlapped w/ compute

        const uint32_t Ab = sb + (kt % STG) * STAGE_BY;
#pragma unroll
        for (int ks = 0; ks < 4; ks++) {
            uint32_t af[4][4];
#pragma unroll
            for (int mc = 0; mc < 4; mc++) {
                const int r = m0w + mc * 16 + (lane & 15);
                const int u = ks * 2 + (lane >> 4);
                LDSM4(af[mc], Ab + r * 128 + ((u ^ (r & 7)) * 16));
            }
            uint32_t bf[2][4];
#pragma unroll
            for (int pr = 0; pr < 2; pr++) {
                const int n = n0w + pr * 16 + ((lane >> 4) & 1) * 8 + (lane & 7);
                const int u = ks * 2 + ((lane >> 3) & 1);
                LDSM4(bf[pr], Ab + 16384 + n * 128 + ((u ^ (n & 7)) * 16));
            }
#pragma unroll
            for (int mc = 0; mc < 4; mc++)
#pragma unroll
                for (int pr = 0; pr < 2; pr++)
#pragma unroll
                    for (int h = 0; h < 2; h++)
                        mma16816(acc[mc][pr * 2 + h], af[mc], &bf[pr][h * 2]);
        }
    }

    // ---- fused epilogue ----
#pragma unroll
    for (int mc = 0; mc < 4; mc++) {
        const int r0 = m0 + m0w + mc * 16 + (lane >> 2);
        const int r1 = r0 + 8;
        const float rs0 = (rowscale && r0 < M) ? rowscale[r0] : 0.f;
        const float rs1 = (rowscale && r1 < M) ? rowscale[r1] : 0.f;
#pragma unroll
        for (int nc = 0; nc < 4; nc++) {
            const int col = n0 + n0w + nc * 8 + (lane & 3) * 2;
            float2 bv = make_float2(0.f, 0.f);
            if (bias) bv = *(const float2*)(bias + col);
#pragma unroll
            for (int half_ = 0; half_ < 2; half_++) {
                const int r = half_ ? r1 : r0;
                if (r >= M) continue;
                const float rs = half_ ? rs1 : rs0;
                float2 v = make_float2(acc[mc][nc][2 * half_], acc[mc][nc][2 * half_ + 1]);
                if (addmat) {
                    float2 a = *(const float2*)(addmat + (long long)r * Nc + col);
                    v.x += a.x * rs; v.y += a.y * rs;
                }
                v.x += bv.x; v.y += bv.y;
                if (relu) { v.x = fmaxf(v.x, 0.f); v.y = fmaxf(v.y, 0.f); }
                if (C)  *(float2*)(C + (long long)r * Nc + col) = v;
                if (Oh) *(__half2*)(Oh + (long long)r * Nc + col) = __floats2half2_rn(v.x, v.y);
            }
        }
    }
}

// ---------------- L2 normalize (D3 = 1024) -----------------------------------
__global__ void l2norm_kernel(const float* __restrict__ H, float* __restrict__ out) {
    const int row = blockIdx.x;
    const float4* h = (const float4*)H + (long long)row * 256;
    float4 v = h[threadIdx.x];
    float s = v.x * v.x + v.y * v.y + v.z * v.z + v.w * v.w;
#pragma unroll
    for (int o = 16; o; o >>= 1) s += __shfl_xor_sync(0xFFFFFFFFu, s, o);
    __shared__ float ws[8];
    if ((threadIdx.x & 31) == 0) ws[threadIdx.x >> 5] = s;
    __syncthreads();
    if (threadIdx.x < 8) {
        float t = ws[threadIdx.x];
#pragma unroll
        for (int o = 4; o; o >>= 1) t += __shfl_xor_sync(0xFFu, t, o);
        if (threadIdx.x == 0) ws[0] = t;
    }
    __syncthreads();
    const float inv = 1.0f / fmaxf(sqrtf(ws[0]), 1e-12f);
    ((float4*)out)[(long long)row * 256 + threadIdx.x] =
        make_float4(v.x * inv, v.y * inv, v.z * inv, v.w * inv);
}

// ---------------- host -------------------------------------------------------
static void run_mma(const __half* A, const __half* B, float* C, __half* Oh,
                    const float* addmat, const float* rowscale,
                    const float* bias, int M, int Nc, int K, int relu) {
    static bool attr_set = false;
    if (!attr_set) {
        cudaFuncSetAttribute(mma_gemm, cudaFuncAttributeMaxDynamicSharedMemorySize, SMEM_TOT);
        attr_set = true;
    }
    dim3 grid(Nc / 128, (M + 127) / 128);
    mma_gemm<<<grid, 256, SMEM_TOT>>>(A, B, C, Oh, addmat, rowscale, bias, M, Nc, K, relu);
}

extern "C" void kernel_launch(void* const* d_in, const int* in_sizes, int n_in,
                              void* d_out, int out_size) {
    const float* x   = (const float*)d_in[0];
    const void*  ei  = d_in[2];
    const float* W1l = (const float*)d_in[3];
    const float* W1r = (const float*)d_in[4];
    const float* b1  = (const float*)d_in[5];
    const float* W2l = (const float*)d_in[6];
    const float* W2r = (const float*)d_in[7];
    const float* b2  = (const float*)d_in[8];
    const float* W3l = (const float*)d_in[9];
    const float* W3r = (const float*)d_in[10];
    const float* b3  = (const float*)d_in[11];

    const int D1 = in_sizes[5];       // 2048
    const int D2 = in_sizes[8];       // 2048
    const int D3 = in_sizes[11];      // 1024
    const int F  = in_sizes[3] / D1;  // 128
    const int N  = in_sizes[0] / F;   // 50000
    const int E  = in_sizes[2] / 2;   // 400000

    float *P, *AGG, *H, *invc;
    cudaGetSymbolAddress((void**)&P, g_P);
    cudaGetSymbolAddress((void**)&AGG, g_AGG);
    cudaGetSymbolAddress((void**)&H, g_H);
    cudaGetSymbolAddress((void**)&invc, g_invcnt);
    __half *Xh, *A1h, *W1, *W2lp, *W2rp, *W3lp, *W3rp;
    cudaGetSymbolAddress((void**)&Xh, g_Xh);
    cudaGetSymbolAddress((void**)&A1h, g_A1h);
    cudaGetSymbolAddress((void**)&W1, g_W1);
    cudaGetSymbolAddress((void**)&W2lp, g_W2l);
    cudaGetSymbolAddress((void**)&W2rp, g_W2r);
    cudaGetSymbolAddress((void**)&W3lp, g_W3l);
    cudaGetSymbolAddress((void**)&W3rp, g_W3r);

    // g_P arena (400 MB) partition, disjoint fp16 regions:
    //   P16 [0, N*D2)      — layer-2/3 GEMM-a outputs (<= 200 MB)
    //   A2h [N*D2, 2*N*D2) — H2 activations (200 MB)
    __half* P16 = (__half*)P;
    __half* A2h = P16 + (long long)N * D2;

    float* out = (float*)d_out;
    const int TPB = 256;
    const int eb = (E + TPB - 1) / TPB;

    // ---- prologue ----
    detect_zero_kernel<<<1, 256>>>((const int*)ei, E < 1024 ? E : 1024, N);
    count_deg_kernel<<<eb, TPB>>>(ei, E);
    scan_inv_kernel<<<1, 1024>>>(N);
    fill_csr_kernel<<<eb, TPB>>>(ei, E);

    // ---- layer 1 prep: Xh = [mean_x | x] fp16, + W1 transpose/convert ----
    const int nodeBlocks = (N + 3) / 4;
    const int w1Tiles = 2 * (D1 / 32) * (F / 32);
    l1_prep_kernel<<<nodeBlocks + w1Tiles, 256>>>(x, N, nodeBlocks, W1l, W1r, F, D1);
    run_mma(Xh, W1, nullptr, A1h, nullptr, nullptr, b1, N, D1, 2 * F, 1);

    // ---- remaining weight conversions ----
    dim3 tb(32, 8);
    wconvT_kernel<<<dim3(D2 / 32, D1 / 32), tb>>>(W2l, W2lp, D1, D2);
    wconvT_kernel<<<dim3(D2 / 32, D1 / 32), tb>>>(W2r, W2rp, D1, D2);
    wconvT_kernel<<<dim3(D3 / 32, D2 / 32), tb>>>(W3l, W3lp, D2, D3);
    wconvT_kernel<<<dim3(D3 / 32, D2 / 32), tb>>>(W3r, W3rp, D2, D3);

    // ---- layer 2: P16 = H1@W2l (fp16); AGG = gather(P16); H2 -> A2h ----
    run_mma(A1h, W2lp, nullptr, P16, nullptr, nullptr, nullptr, N, D2, D1, 0);
    gather_sum_h_kernel<<<dim3(N, D2 / 1024), 128>>>(P16, AGG, D2);
    run_mma(A1h, W2rp, nullptr, A2h, AGG, invc, b2, N, D2, D1, 1);

    // ---- layer 3: P16 = H2@W3l (fp16); AGG = gather(P16); H3 -> H ----
    run_mma(A2h, W3lp, nullptr, P16, nullptr, nullptr, nullptr, N, D3, D2, 0);
    gather_sum_h_kernel<<<dim3(N, D3 / 1024), 128>>>(P16, AGG, D3);
    run_mma(A2h, W3rp, H, nullptr, AGG, invc, b3, N, D3, D2, 1);

    // ---- normalize ----
    l2norm_kernel<<<N, 256>>>(H, out);
    (void)n_in; (void)out_size;
}